// round 3
// baseline (speedup 1.0000x reference)
#include <cuda_runtime.h>
#include <cuda_bf16.h>

// Problem constants
#define BDIM  4096
#define TDIM  32
#define KDIM  16
#define DDIM  512
#define HDIM  1024   // = 2*D
#define H2DIM 2048   // = 2*H

// Scratch (device globals: allocation-free rule)
__device__ float g_hat_buf[BDIM * DDIM];    // (B, D)
__device__ float E1_buf[BDIM * HDIM];       // g_hat @ W1[:512] + b1
__device__ float e_buf[BDIM * TDIM];        // attention scores
__device__ float xhat_buf[BDIM * DDIM];     // attention-pooled x
__device__ float E2_buf[BDIM * H2DIM];      // x_hat @ M1[:512] + c1

// ---------------------------------------------------------------------------
// K1: g_hat = mean_k G  (B*D threads)
// ---------------------------------------------------------------------------
__global__ void gmean_kernel(const float* __restrict__ G, float* __restrict__ out) {
    int idx = blockIdx.x * blockDim.x + threadIdx.x;     // over B*D
    int b = idx / DDIM;
    int d = idx - b * DDIM;
    const float* g = G + (size_t)b * KDIM * DDIM + d;
    float s = 0.f;
#pragma unroll
    for (int k = 0; k < KDIM; k++) s += g[k * DDIM];
    out[idx] = s * (1.0f / KDIM);
}

// ---------------------------------------------------------------------------
// K2/K5: C(M,N) = A(M,512) @ W(512,N) + bias(N).   BM=BN=64, BK=16, 256 thr.
// ---------------------------------------------------------------------------
__global__ void __launch_bounds__(256) sgemm_bias_kernel(
    const float* __restrict__ A, int lda,
    const float* __restrict__ W, int ldw,
    const float* __restrict__ bias,
    float* __restrict__ C, int N, int Kd)
{
    const int BM = 64, BN = 64, BK = 16;
    __shared__ float As[BM][BK + 1];
    __shared__ float Ws[BK][BN];
    int tx = threadIdx.x & 15, ty = threadIdx.x >> 4;
    int rb = blockIdx.y * BM;
    int cb = blockIdx.x * BN;

    int la_m = threadIdx.x >> 2;
    int la_q = (threadIdx.x & 3) << 2;
    int lw_k = threadIdx.x >> 4;
    int lw_q = (threadIdx.x & 15) << 2;

    float acc[4][4] = {};
    for (int k0 = 0; k0 < Kd; k0 += BK) {
        float4 av = *(const float4*)&A[(size_t)(rb + la_m) * lda + k0 + la_q];
        As[la_m][la_q + 0] = av.x; As[la_m][la_q + 1] = av.y;
        As[la_m][la_q + 2] = av.z; As[la_m][la_q + 3] = av.w;
        *(float4*)&Ws[lw_k][lw_q] =
            *(const float4*)&W[(size_t)(k0 + lw_k) * ldw + cb + lw_q];
        __syncthreads();
#pragma unroll
        for (int k = 0; k < BK; k++) {
            float4 wv = *(const float4*)&Ws[k][tx << 2];
            float a0 = As[ty * 4 + 0][k], a1 = As[ty * 4 + 1][k];
            float a2 = As[ty * 4 + 2][k], a3 = As[ty * 4 + 3][k];
            acc[0][0] += a0 * wv.x; acc[0][1] += a0 * wv.y; acc[0][2] += a0 * wv.z; acc[0][3] += a0 * wv.w;
            acc[1][0] += a1 * wv.x; acc[1][1] += a1 * wv.y; acc[1][2] += a1 * wv.z; acc[1][3] += a1 * wv.w;
            acc[2][0] += a2 * wv.x; acc[2][1] += a2 * wv.y; acc[2][2] += a2 * wv.z; acc[2][3] += a2 * wv.w;
            acc[3][0] += a3 * wv.x; acc[3][1] += a3 * wv.y; acc[3][2] += a3 * wv.z; acc[3][3] += a3 * wv.w;
        }
        __syncthreads();
    }
    float4 bv = *(const float4*)&bias[cb + (tx << 2)];
#pragma unroll
    for (int i = 0; i < 4; i++) {
        int row = rb + ty * 4 + i;
        float4 o;
        o.x = acc[i][0] + bv.x; o.y = acc[i][1] + bv.y;
        o.z = acc[i][2] + bv.z; o.w = acc[i][3] + bv.w;
        *(float4*)&C[(size_t)row * N + cb + (tx << 2)] = o;
    }
}

// ---------------------------------------------------------------------------
// K3/K6: out[row] = sum_n relu( (A@W)[row,n] + Eb[row/RPB, n] ) * wvec[n] (+ sc)
// A: (M,512) row-major; W: (512,N) row-major; loops all N tiles per block.
// ---------------------------------------------------------------------------
template <int ROWS_PER_B>
__global__ void __launch_bounds__(256) fused_reduce_kernel(
    const float* __restrict__ A,
    const float* __restrict__ W,
    const float* __restrict__ Eb,
    const float* __restrict__ wvec,
    const float* __restrict__ addsc,   // nullable device scalar
    float* __restrict__ out,
    int N)
{
    const int BM = 64, BN = 64, BK = 16, KD = DDIM;
    __shared__ float As[BM][BK + 1];
    __shared__ float Ws[BK][BN];
    int tx = threadIdx.x & 15, ty = threadIdx.x >> 4;
    int rb = blockIdx.x * BM;

    int la_m = threadIdx.x >> 2;
    int la_q = (threadIdx.x & 3) << 2;
    int lw_k = threadIdx.x >> 4;
    int lw_q = (threadIdx.x & 15) << 2;

    int brow = (rb + ty * 4) / ROWS_PER_B;   // constant across i=0..3 (aligned)

    float rowsum[4] = {0.f, 0.f, 0.f, 0.f};
    int ntiles = N / BN;
    for (int nt = 0; nt < ntiles; nt++) {
        int cb = nt * BN;
        float acc[4][4] = {};
        for (int k0 = 0; k0 < KD; k0 += BK) {
            float4 av = *(const float4*)&A[(size_t)(rb + la_m) * KD + k0 + la_q];
            As[la_m][la_q + 0] = av.x; As[la_m][la_q + 1] = av.y;
            As[la_m][la_q + 2] = av.z; As[la_m][la_q + 3] = av.w;
            *(float4*)&Ws[lw_k][lw_q] =
                *(const float4*)&W[(size_t)(k0 + lw_k) * N + cb + lw_q];
            __syncthreads();
#pragma unroll
            for (int k = 0; k < BK; k++) {
                float4 wv = *(const float4*)&Ws[k][tx << 2];
                float a0 = As[ty * 4 + 0][k], a1 = As[ty * 4 + 1][k];
                float a2 = As[ty * 4 + 2][k], a3 = As[ty * 4 + 3][k];
                acc[0][0] += a0 * wv.x; acc[0][1] += a0 * wv.y; acc[0][2] += a0 * wv.z; acc[0][3] += a0 * wv.w;
                acc[1][0] += a1 * wv.x; acc[1][1] += a1 * wv.y; acc[1][2] += a1 * wv.z; acc[1][3] += a1 * wv.w;
                acc[2][0] += a2 * wv.x; acc[2][1] += a2 * wv.y; acc[2][2] += a2 * wv.z; acc[2][3] += a2 * wv.w;
                acc[3][0] += a3 * wv.x; acc[3][1] += a3 * wv.y; acc[3][2] += a3 * wv.z; acc[3][3] += a3 * wv.w;
            }
            __syncthreads();
        }
        float4 ebv = *(const float4*)&Eb[(size_t)brow * N + cb + (tx << 2)];
        float4 wv2 = *(const float4*)&wvec[cb + (tx << 2)];
#pragma unroll
        for (int i = 0; i < 4; i++) {
            rowsum[i] += fmaxf(acc[i][0] + ebv.x, 0.f) * wv2.x
                       + fmaxf(acc[i][1] + ebv.y, 0.f) * wv2.y
                       + fmaxf(acc[i][2] + ebv.z, 0.f) * wv2.z
                       + fmaxf(acc[i][3] + ebv.w, 0.f) * wv2.w;
        }
    }
    // reduce across the 16 tx lanes (they sit in one 16-lane half of a warp)
#pragma unroll
    for (int i = 0; i < 4; i++) {
        float s = rowsum[i];
#pragma unroll
        for (int off = 8; off >= 1; off >>= 1)
            s += __shfl_xor_sync(0xffffffffu, s, off, 16);
        if (tx == 0) {
            float addv = addsc ? *addsc : 0.f;
            out[rb + ty * 4 + i] = s + addv;
        }
    }
}

// ---------------------------------------------------------------------------
// K4: per-b softmax over T=32 then x_hat = sum_t alpha_t * X[b,t,:]
// ---------------------------------------------------------------------------
__global__ void softmax_xhat_kernel(const float* __restrict__ e,
                                    const float* __restrict__ X,
                                    float* __restrict__ xhat)
{
    int b = blockIdx.x;
    __shared__ float alpha[TDIM];
    int tid = threadIdx.x;   // 128 threads
    if (tid < 32) {
        float v = e[b * TDIM + tid];
        float m = v;
#pragma unroll
        for (int off = 16; off >= 1; off >>= 1)
            m = fmaxf(m, __shfl_xor_sync(0xffffffffu, m, off));
        float ex = __expf(v - m);
        float s = ex;
#pragma unroll
        for (int off = 16; off >= 1; off >>= 1)
            s += __shfl_xor_sync(0xffffffffu, s, off);
        alpha[tid] = ex / s;
    }
    __syncthreads();
    const float* Xb = X + (size_t)b * TDIM * DDIM;
#pragma unroll 1
    for (int d = tid; d < DDIM; d += 128) {
        float s = 0.f;
#pragma unroll
        for (int t = 0; t < TDIM; t++) s += alpha[t] * Xb[t * DDIM + d];
        xhat[(size_t)b * DDIM + d] = s;
    }
}

// ---------------------------------------------------------------------------
extern "C" void kernel_launch(void* const* d_in, const int* in_sizes, int n_in,
                              void* d_out, int out_size)
{
    const float* X  = (const float*)d_in[0];
    const float* G  = (const float*)d_in[1];
    const float* W1 = (const float*)d_in[2];
    const float* b1 = (const float*)d_in[3];
    const float* w2 = (const float*)d_in[4];
    // d_in[5] = b2: softmax shift-invariant, unused
    const float* M1 = (const float*)d_in[6];
    const float* c1 = (const float*)d_in[7];
    const float* m2 = (const float*)d_in[8];
    const float* c2 = (const float*)d_in[9];
    float* out = (float*)d_out;

    float *g_hat, *E1, *ebuf, *xh, *E2;
    cudaGetSymbolAddress((void**)&g_hat, g_hat_buf);
    cudaGetSymbolAddress((void**)&E1,    E1_buf);
    cudaGetSymbolAddress((void**)&ebuf,  e_buf);
    cudaGetSymbolAddress((void**)&xh,    xhat_buf);
    cudaGetSymbolAddress((void**)&E2,    E2_buf);

    // K1: g_hat
    gmean_kernel<<<(BDIM * DDIM) / 256, 256>>>(G, g_hat);

    // K2: E1 = g_hat @ W1[:512] + b1    (4096 x 1024)
    {
        dim3 grid(HDIM / 64, BDIM / 64);
        sgemm_bias_kernel<<<grid, 256>>>(g_hat, DDIM, W1, HDIM, b1, E1, HDIM, DDIM);
    }

    // K3: e[b,t] = sum_h relu( X@W1[512:] + E1 ) * w2   (M = 131072)
    fused_reduce_kernel<TDIM><<<(BDIM * TDIM) / 64, 256>>>(
        X, W1 + (size_t)DDIM * HDIM, E1, w2, nullptr, ebuf, HDIM);

    // K4: softmax over T + x_hat
    softmax_xhat_kernel<<<BDIM, 128>>>(ebuf, X, xh);

    // K5: E2 = x_hat @ M1[:512] + c1    (4096 x 2048)
    {
        dim3 grid(H2DIM / 64, BDIM / 64);
        sgemm_bias_kernel<<<grid, 256>>>(xh, DDIM, M1, H2DIM, c1, E2, H2DIM, DDIM);
    }

    // K6: logits[b,k] = sum_j relu( G@M1[512:] + E2 ) * m2 + c2   (M = 65536)
    fused_reduce_kernel<KDIM><<<(BDIM * KDIM) / 64, 256>>>(
        G, M1 + (size_t)DDIM * H2DIM, E2, m2, c2, out, H2DIM);
}

// round 4
// speedup vs baseline: 1.4525x; 1.4525x over previous
#include <cuda_runtime.h>
#include <cuda_bf16.h>
#include <cstdint>

// Problem constants
#define BDIM  4096
#define TDIM  32
#define KDIM  16
#define DDIM  512
#define HDIM  1024   // = 2*D
#define H2DIM 2048   // = 2*H

// ---------------------------------------------------------------------------
// Scratch (device globals: allocation-free rule)
// ---------------------------------------------------------------------------
__device__ float g_hat_buf[BDIM * DDIM];
__device__ float E1_buf[BDIM * HDIM];
__device__ float e_buf[BDIM * TDIM];
__device__ float xhat_buf[BDIM * DDIM];
__device__ float E2_buf[BDIM * H2DIM];

// split-bf16 operand buffers
__device__ __nv_bfloat16 Xh_buf[BDIM * TDIM * DDIM];
__device__ __nv_bfloat16 Xl_buf[BDIM * TDIM * DDIM];
__device__ __nv_bfloat16 Gh_buf[BDIM * KDIM * DDIM];
__device__ __nv_bfloat16 Gl_buf[BDIM * KDIM * DDIM];
__device__ __nv_bfloat16 W1h_buf[DDIM * HDIM];
__device__ __nv_bfloat16 W1l_buf[DDIM * HDIM];
__device__ __nv_bfloat16 M1h_buf[DDIM * H2DIM];
__device__ __nv_bfloat16 M1l_buf[DDIM * H2DIM];

// ---------------------------------------------------------------------------
// split: hi = bf16(x); lo = bf16(x - hi)
// ---------------------------------------------------------------------------
__global__ void split_bf16_kernel(const float* __restrict__ src,
                                  __nv_bfloat16* __restrict__ hi,
                                  __nv_bfloat16* __restrict__ lo)
{
    int i = blockIdx.x * blockDim.x + threadIdx.x;   // one float4 per thread
    float4 v = ((const float4*)src)[i];
    __nv_bfloat16 h[4], l[4];
    float x;
    x = v.x; h[0] = __float2bfloat16(x); l[0] = __float2bfloat16(x - __bfloat162float(h[0]));
    x = v.y; h[1] = __float2bfloat16(x); l[1] = __float2bfloat16(x - __bfloat162float(h[1]));
    x = v.z; h[2] = __float2bfloat16(x); l[2] = __float2bfloat16(x - __bfloat162float(h[2]));
    x = v.w; h[3] = __float2bfloat16(x); l[3] = __float2bfloat16(x - __bfloat162float(h[3]));
    ((uint2*)hi)[i] = *(uint2*)h;
    ((uint2*)lo)[i] = *(uint2*)l;
}

// ---------------------------------------------------------------------------
// K1: g_hat = mean_k G
// ---------------------------------------------------------------------------
__global__ void gmean_kernel(const float* __restrict__ G, float* __restrict__ out) {
    int idx = blockIdx.x * blockDim.x + threadIdx.x;
    int b = idx / DDIM;
    int d = idx - b * DDIM;
    const float* g = G + (size_t)b * KDIM * DDIM + d;
    float s = 0.f;
#pragma unroll
    for (int k = 0; k < KDIM; k++) s += g[k * DDIM];
    out[idx] = s * (1.0f / KDIM);
}

// ---------------------------------------------------------------------------
// K2/K5: small fp32 GEMM C(M,N) = A(M,512) @ W(512,N) + bias(N)
// ---------------------------------------------------------------------------
__global__ void __launch_bounds__(256) sgemm_bias_kernel(
    const float* __restrict__ A, int lda,
    const float* __restrict__ W, int ldw,
    const float* __restrict__ bias,
    float* __restrict__ C, int N, int Kd)
{
    const int BM = 64, BN = 64, BK = 16;
    __shared__ float As[BM][BK + 1];
    __shared__ float Ws[BK][BN];
    int tx = threadIdx.x & 15, ty = threadIdx.x >> 4;
    int rb = blockIdx.y * BM;
    int cb = blockIdx.x * BN;

    int la_m = threadIdx.x >> 2;
    int la_q = (threadIdx.x & 3) << 2;
    int lw_k = threadIdx.x >> 4;
    int lw_q = (threadIdx.x & 15) << 2;

    float acc[4][4] = {};
    for (int k0 = 0; k0 < Kd; k0 += BK) {
        float4 av = *(const float4*)&A[(size_t)(rb + la_m) * lda + k0 + la_q];
        As[la_m][la_q + 0] = av.x; As[la_m][la_q + 1] = av.y;
        As[la_m][la_q + 2] = av.z; As[la_m][la_q + 3] = av.w;
        *(float4*)&Ws[lw_k][lw_q] =
            *(const float4*)&W[(size_t)(k0 + lw_k) * ldw + cb + lw_q];
        __syncthreads();
#pragma unroll
        for (int k = 0; k < BK; k++) {
            float4 wv = *(const float4*)&Ws[k][tx << 2];
            float a0 = As[ty * 4 + 0][k], a1 = As[ty * 4 + 1][k];
            float a2 = As[ty * 4 + 2][k], a3 = As[ty * 4 + 3][k];
            acc[0][0] += a0 * wv.x; acc[0][1] += a0 * wv.y; acc[0][2] += a0 * wv.z; acc[0][3] += a0 * wv.w;
            acc[1][0] += a1 * wv.x; acc[1][1] += a1 * wv.y; acc[1][2] += a1 * wv.z; acc[1][3] += a1 * wv.w;
            acc[2][0] += a2 * wv.x; acc[2][1] += a2 * wv.y; acc[2][2] += a2 * wv.z; acc[2][3] += a2 * wv.w;
            acc[3][0] += a3 * wv.x; acc[3][1] += a3 * wv.y; acc[3][2] += a3 * wv.z; acc[3][3] += a3 * wv.w;
        }
        __syncthreads();
    }
    float4 bv = *(const float4*)&bias[cb + (tx << 2)];
#pragma unroll
    for (int i = 0; i < 4; i++) {
        int row = rb + ty * 4 + i;
        float4 o;
        o.x = acc[i][0] + bv.x; o.y = acc[i][1] + bv.y;
        o.z = acc[i][2] + bv.z; o.w = acc[i][3] + bv.w;
        *(float4*)&C[(size_t)row * N + cb + (tx << 2)] = o;
    }
}

// ---------------------------------------------------------------------------
// bf16 m16n8k16 MMA wrapper
// ---------------------------------------------------------------------------
__device__ __forceinline__ void mma16816(float c[4], const unsigned a[4], const unsigned b[2]) {
    asm volatile(
        "mma.sync.aligned.m16n8k16.row.col.f32.bf16.bf16.f32 "
        "{%0,%1,%2,%3}, {%4,%5,%6,%7}, {%8,%9}, {%0,%1,%2,%3};\n"
        : "+f"(c[0]), "+f"(c[1]), "+f"(c[2]), "+f"(c[3])
        : "r"(a[0]), "r"(a[1]), "r"(a[2]), "r"(a[3]), "r"(b[0]), "r"(b[1]));
}

// ---------------------------------------------------------------------------
// K3/K6: split-bf16 tensor-core GEMM with fused relu-dot-reduce epilogue.
// Logical K = 1536: [Ah, Ah, Al] x [Bh, Bl, Bh] = AhBh + AhBl + AlBh.
// out[row] = sum_n relu( (A@W)[row,n] + Eb[row>>RPB_SHIFT, n] ) * wvec[n] (+sc)
// BM=128, BN=128, BK=32; 8 warps (4m x 2n), warp tile 32x64.
// ---------------------------------------------------------------------------
template <int RPB_SHIFT>
__global__ void __launch_bounds__(256, 2) fused_reduce_mma(
    const __nv_bfloat16* __restrict__ Ah, const __nv_bfloat16* __restrict__ Al,
    const __nv_bfloat16* __restrict__ Bh, const __nv_bfloat16* __restrict__ Bl,
    const float* __restrict__ Eb,
    const float* __restrict__ wvec,
    const float* __restrict__ addsc,
    float* __restrict__ out,
    int N)
{
    __shared__ __nv_bfloat16 As[128][40];   // [m][k], pad->20-word stride (conflict-free)
    __shared__ __nv_bfloat16 Bs[128][40];   // [n][k]
    __shared__ float red[128][2];

    const int tid   = threadIdx.x;
    const int lane  = tid & 31;
    const int wid   = tid >> 5;
    const int warp_m = wid & 3;     // 0..3 -> rows warp_m*32
    const int warp_n = wid >> 2;    // 0..1 -> cols warp_n*64
    const int lq = lane >> 2;       // 0..7
    const int lr = lane & 3;        // 0..3
    const int rb = blockIdx.x * 128;

    // global A-load mapping: thread -> (row, 4 consecutive k)
    const int a_row = tid >> 3;            // 0..31 (x4 passes)
    const int a_kq  = (tid & 7) << 2;      // 0..28 step 4
    // global B-load mapping: thread -> (k, 16 consecutive n)
    const int b_k  = tid & 31;
    const int b_nb = (tid >> 5) << 4;      // 0..112 step 16

    float rs[2][2] = {{0.f, 0.f}, {0.f, 0.f}};

    const int ntiles = N >> 7;
    for (int nt = 0; nt < ntiles; nt++) {
        const int cb = nt << 7;
        float c[2][8][4];
#pragma unroll
        for (int mi = 0; mi < 2; mi++)
#pragma unroll
            for (int ni = 0; ni < 8; ni++)
#pragma unroll
                for (int e = 0; e < 4; e++) c[mi][ni][e] = 0.f;

#pragma unroll 1
        for (int reg = 0; reg < 3; reg++) {
            const __nv_bfloat16* Ap = (reg < 2) ? Ah : Al;
            const __nv_bfloat16* Bp = (reg == 1) ? Bl : Bh;
#pragma unroll 1
            for (int koff = 0; koff < DDIM; koff += 32) {
                // stage A tile (128 x 32)
#pragma unroll
                for (int r4 = 0; r4 < 4; r4++) {
                    int row = a_row + r4 * 32;
                    *(uint2*)&As[row][a_kq] =
                        *(const uint2*)&Ap[(size_t)(rb + row) * DDIM + koff + a_kq];
                }
                // stage B tile (32 x 128), transposed into [n][k]
#pragma unroll
                for (int j = 0; j < 2; j++) {
                    uint4 v = *(const uint4*)&Bp[(size_t)(koff + b_k) * N + cb + b_nb + j * 8];
                    __nv_bfloat16 t8[8];
                    *(uint4*)t8 = v;
#pragma unroll
                    for (int e = 0; e < 8; e++) Bs[b_nb + j * 8 + e][b_k] = t8[e];
                }
                __syncthreads();

#pragma unroll
                for (int kk = 0; kk < 32; kk += 16) {
                    unsigned a[2][4], b[8][2];
#pragma unroll
                    for (int mi = 0; mi < 2; mi++) {
                        int r0 = warp_m * 32 + mi * 16 + lq;
                        a[mi][0] = *(const unsigned*)&As[r0][kk + lr * 2];
                        a[mi][1] = *(const unsigned*)&As[r0 + 8][kk + lr * 2];
                        a[mi][2] = *(const unsigned*)&As[r0][kk + lr * 2 + 8];
                        a[mi][3] = *(const unsigned*)&As[r0 + 8][kk + lr * 2 + 8];
                    }
#pragma unroll
                    for (int ni = 0; ni < 8; ni++) {
                        int col = warp_n * 64 + ni * 8 + lq;
                        b[ni][0] = *(const unsigned*)&Bs[col][kk + lr * 2];
                        b[ni][1] = *(const unsigned*)&Bs[col][kk + lr * 2 + 8];
                    }
#pragma unroll
                    for (int mi = 0; mi < 2; mi++)
#pragma unroll
                        for (int ni = 0; ni < 8; ni++)
                            mma16816(c[mi][ni], a[mi], b[ni]);
                }
                __syncthreads();
            }
        }

        // fused epilogue: relu(acc + Eb) . wvec, accumulated per row
#pragma unroll
        for (int mi = 0; mi < 2; mi++) {
            int row0 = rb + warp_m * 32 + mi * 16 + lq;
            int row1 = row0 + 8;
            const float* Eb0 = Eb + (size_t)(row0 >> RPB_SHIFT) * N;
            const float* Eb1 = Eb + (size_t)(row1 >> RPB_SHIFT) * N;
#pragma unroll
            for (int ni = 0; ni < 8; ni++) {
                int col = cb + warp_n * 64 + ni * 8 + lr * 2;
                float2 e0 = *(const float2*)&Eb0[col];
                float2 e1 = *(const float2*)&Eb1[col];
                float2 wv = *(const float2*)&wvec[col];
                rs[mi][0] += fmaxf(c[mi][ni][0] + e0.x, 0.f) * wv.x
                           + fmaxf(c[mi][ni][1] + e0.y, 0.f) * wv.y;
                rs[mi][1] += fmaxf(c[mi][ni][2] + e1.x, 0.f) * wv.x
                           + fmaxf(c[mi][ni][3] + e1.y, 0.f) * wv.y;
            }
        }
    }

    // reduce across the 4 lanes sharing each row (lr dimension)
#pragma unroll
    for (int mi = 0; mi < 2; mi++)
#pragma unroll
        for (int h = 0; h < 2; h++) {
            float s = rs[mi][h];
            s += __shfl_xor_sync(0xffffffffu, s, 1);
            s += __shfl_xor_sync(0xffffffffu, s, 2);
            if (lr == 0) red[warp_m * 32 + mi * 16 + h * 8 + lq][warp_n] = s;
        }
    __syncthreads();
    if (tid < 128) {
        float addv = addsc ? *addsc : 0.f;
        out[rb + tid] = red[tid][0] + red[tid][1] + addv;
    }
}

// ---------------------------------------------------------------------------
// K4: per-b softmax over T=32 then x_hat = sum_t alpha_t * X[b,t,:]
// ---------------------------------------------------------------------------
__global__ void softmax_xhat_kernel(const float* __restrict__ e,
                                    const float* __restrict__ X,
                                    float* __restrict__ xhat)
{
    int b = blockIdx.x;
    __shared__ float alpha[TDIM];
    int tid = threadIdx.x;   // 128 threads
    if (tid < 32) {
        float v = e[b * TDIM + tid];
        float m = v;
#pragma unroll
        for (int off = 16; off >= 1; off >>= 1)
            m = fmaxf(m, __shfl_xor_sync(0xffffffffu, m, off));
        float ex = __expf(v - m);
        float s = ex;
#pragma unroll
        for (int off = 16; off >= 1; off >>= 1)
            s += __shfl_xor_sync(0xffffffffu, s, off);
        alpha[tid] = ex / s;
    }
    __syncthreads();
    const float* Xb = X + (size_t)b * TDIM * DDIM;
#pragma unroll 1
    for (int d = tid; d < DDIM; d += 128) {
        float s = 0.f;
#pragma unroll
        for (int t = 0; t < TDIM; t++) s += alpha[t] * Xb[t * DDIM + d];
        xhat[(size_t)b * DDIM + d] = s;
    }
}

// ---------------------------------------------------------------------------
extern "C" void kernel_launch(void* const* d_in, const int* in_sizes, int n_in,
                              void* d_out, int out_size)
{
    const float* X  = (const float*)d_in[0];
    const float* G  = (const float*)d_in[1];
    const float* W1 = (const float*)d_in[2];
    const float* b1 = (const float*)d_in[3];
    const float* w2 = (const float*)d_in[4];
    // d_in[5] = b2: softmax shift-invariant, unused
    const float* M1 = (const float*)d_in[6];
    const float* c1 = (const float*)d_in[7];
    const float* m2 = (const float*)d_in[8];
    const float* c2 = (const float*)d_in[9];
    float* out = (float*)d_out;

    float *g_hat, *E1, *ebuf, *xh, *E2;
    cudaGetSymbolAddress((void**)&g_hat, g_hat_buf);
    cudaGetSymbolAddress((void**)&E1,    E1_buf);
    cudaGetSymbolAddress((void**)&ebuf,  e_buf);
    cudaGetSymbolAddress((void**)&xh,    xhat_buf);
    cudaGetSymbolAddress((void**)&E2,    E2_buf);

    __nv_bfloat16 *Xh, *Xl, *Gh, *Gl, *W1h, *W1l, *M1h, *M1l;
    cudaGetSymbolAddress((void**)&Xh,  Xh_buf);
    cudaGetSymbolAddress((void**)&Xl,  Xl_buf);
    cudaGetSymbolAddress((void**)&Gh,  Gh_buf);
    cudaGetSymbolAddress((void**)&Gl,  Gl_buf);
    cudaGetSymbolAddress((void**)&W1h, W1h_buf);
    cudaGetSymbolAddress((void**)&W1l, W1l_buf);
    cudaGetSymbolAddress((void**)&M1h, M1h_buf);
    cudaGetSymbolAddress((void**)&M1l, M1l_buf);

    // split-bf16 conversions (X, G, and the used weight halves)
    split_bf16_kernel<<<(BDIM * TDIM * DDIM / 4) / 256, 256>>>(X, Xh, Xl);
    split_bf16_kernel<<<(BDIM * KDIM * DDIM / 4) / 256, 256>>>(G, Gh, Gl);
    split_bf16_kernel<<<(DDIM * HDIM / 4) / 256, 256>>>(W1 + (size_t)DDIM * HDIM, W1h, W1l);
    split_bf16_kernel<<<(DDIM * H2DIM / 4) / 256, 256>>>(M1 + (size_t)DDIM * H2DIM, M1h, M1l);

    // K1: g_hat
    gmean_kernel<<<(BDIM * DDIM) / 256, 256>>>(G, g_hat);

    // K2: E1 = g_hat @ W1[:512] + b1   (4096 x 1024, fp32)
    {
        dim3 grid(HDIM / 64, BDIM / 64);
        sgemm_bias_kernel<<<grid, 256>>>(g_hat, DDIM, W1, HDIM, b1, E1, HDIM, DDIM);
    }

    // K3: e[b,t] = sum_h relu( X@W1[512:] + E1 ) * w2   (M = 131072, tensor core)
    fused_reduce_mma<5><<<(BDIM * TDIM) / 128, 256>>>(
        Xh, Xl, W1h, W1l, E1, w2, nullptr, ebuf, HDIM);

    // K4: softmax over T + x_hat
    softmax_xhat_kernel<<<BDIM, 128>>>(ebuf, X, xh);

    // K5: E2 = x_hat @ M1[:512] + c1   (4096 x 2048, fp32)
    {
        dim3 grid(H2DIM / 64, BDIM / 64);
        sgemm_bias_kernel<<<grid, 256>>>(xh, DDIM, M1, H2DIM, c1, E2, H2DIM, DDIM);
    }

    // K6: logits[b,k] = sum_j relu( G@M1[512:] + E2 ) * m2 + c2  (M = 65536, tensor core)
    fused_reduce_mma<4><<<(BDIM * KDIM) / 128, 256>>>(
        Gh, Gl, M1h, M1l, E2, m2, c2, out, H2DIM);
}

// round 5
// speedup vs baseline: 3.0812x; 2.1213x over previous
#include <cuda_runtime.h>
#include <cuda_bf16.h>
#include <cstdint>

// Problem constants
#define BDIM  4096
#define TDIM  32
#define KDIM  16
#define DDIM  512
#define HDIM  1024   // = 2*D
#define H2DIM 2048   // = 2*H

// ---------------------------------------------------------------------------
// Scratch (device globals: allocation-free rule)
// ---------------------------------------------------------------------------
__device__ float E1_buf[BDIM * HDIM];
__device__ float E2_buf[BDIM * H2DIM];
__device__ float e_buf[BDIM * TDIM];

__device__ __nv_bfloat16 Xh_buf[BDIM * TDIM * DDIM];
__device__ __nv_bfloat16 Xl_buf[BDIM * TDIM * DDIM];
__device__ __nv_bfloat16 Gh_buf[BDIM * KDIM * DDIM];
__device__ __nv_bfloat16 Gl_buf[BDIM * KDIM * DDIM];
__device__ __nv_bfloat16 W1h_buf[2 * DDIM * HDIM];   // full W1 (1024 x 1024)
__device__ __nv_bfloat16 W1l_buf[2 * DDIM * HDIM];
__device__ __nv_bfloat16 M1h_buf[2 * DDIM * H2DIM];  // full M1 (1024 x 2048)
__device__ __nv_bfloat16 M1l_buf[2 * DDIM * H2DIM];
__device__ __nv_bfloat16 ghh_buf[BDIM * DDIM];
__device__ __nv_bfloat16 ghl_buf[BDIM * DDIM];
__device__ __nv_bfloat16 xhh_buf[BDIM * DDIM];
__device__ __nv_bfloat16 xhl_buf[BDIM * DDIM];

// ---------------------------------------------------------------------------
// PTX helpers
// ---------------------------------------------------------------------------
__device__ __forceinline__ void cp16(uint32_t dst, const void* src) {
    asm volatile("cp.async.cg.shared.global [%0], [%1], 16;\n"
                 :: "r"(dst), "l"(src) : "memory");
}
__device__ __forceinline__ void cp_commit() {
    asm volatile("cp.async.commit_group;\n" ::: "memory");
}
__device__ __forceinline__ void cp_wait1() {
    asm volatile("cp.async.wait_group 1;\n" ::: "memory");
}
__device__ __forceinline__ void ldsm_x4(unsigned& d0, unsigned& d1, unsigned& d2,
                                        unsigned& d3, uint32_t addr) {
    asm volatile("ldmatrix.sync.aligned.m8n8.x4.shared.b16 {%0,%1,%2,%3}, [%4];\n"
                 : "=r"(d0), "=r"(d1), "=r"(d2), "=r"(d3) : "r"(addr));
}
__device__ __forceinline__ void ldsm_x4_t(unsigned& d0, unsigned& d1, unsigned& d2,
                                          unsigned& d3, uint32_t addr) {
    asm volatile("ldmatrix.sync.aligned.m8n8.x4.trans.shared.b16 {%0,%1,%2,%3}, [%4];\n"
                 : "=r"(d0), "=r"(d1), "=r"(d2), "=r"(d3) : "r"(addr));
}
__device__ __forceinline__ void mma16816(float c[4], const unsigned a[4], const unsigned b[2]) {
    asm volatile(
        "mma.sync.aligned.m16n8k16.row.col.f32.bf16.bf16.f32 "
        "{%0,%1,%2,%3}, {%4,%5,%6,%7}, {%8,%9}, {%0,%1,%2,%3};\n"
        : "+f"(c[0]), "+f"(c[1]), "+f"(c[2]), "+f"(c[3])
        : "r"(a[0]), "r"(a[1]), "r"(a[2]), "r"(a[3]), "r"(b[0]), "r"(b[1]));
}

// ---------------------------------------------------------------------------
// split: hi = bf16(x); lo = bf16(x - hi)
// ---------------------------------------------------------------------------
__global__ void split_bf16_kernel(const float* __restrict__ src,
                                  __nv_bfloat16* __restrict__ hi,
                                  __nv_bfloat16* __restrict__ lo)
{
    int i = blockIdx.x * blockDim.x + threadIdx.x;
    float4 v = ((const float4*)src)[i];
    __nv_bfloat16 h[4], l[4];
    float x;
    x = v.x; h[0] = __float2bfloat16(x); l[0] = __float2bfloat16(x - __bfloat162float(h[0]));
    x = v.y; h[1] = __float2bfloat16(x); l[1] = __float2bfloat16(x - __bfloat162float(h[1]));
    x = v.z; h[2] = __float2bfloat16(x); l[2] = __float2bfloat16(x - __bfloat162float(h[2]));
    x = v.w; h[3] = __float2bfloat16(x); l[3] = __float2bfloat16(x - __bfloat162float(h[3]));
    ((uint2*)hi)[i] = *(uint2*)h;
    ((uint2*)lo)[i] = *(uint2*)l;
}

// ---------------------------------------------------------------------------
// K1: g_hat = mean_k G, written directly as split-bf16
// ---------------------------------------------------------------------------
__global__ void gmean_split_kernel(const float* __restrict__ G,
                                   __nv_bfloat16* __restrict__ h,
                                   __nv_bfloat16* __restrict__ l)
{
    int idx = blockIdx.x * blockDim.x + threadIdx.x;   // over B*D
    int b = idx >> 9;
    int d = idx & 511;
    const float* g = G + (size_t)b * KDIM * DDIM + d;
    float s = 0.f;
#pragma unroll
    for (int k = 0; k < KDIM; k++) s += g[k * DDIM];
    s *= (1.0f / KDIM);
    __nv_bfloat16 hh = __float2bfloat16(s);
    h[idx] = hh;
    l[idx] = __float2bfloat16(s - __bfloat162float(hh));
}

// ---------------------------------------------------------------------------
// Tensor-core split-bf16 GEMM, BM=128, BN=128, BK=32, 8 warps (4m x 2n).
// Logical K = 1536: AhBh + AhBl + AlBh (3 passes over single-staged tiles).
// REDUCE=true : out[row] = sum_n relu(acc + Eb[row>>RPB_SHIFT, n]) * wvec[n] (+sc)
//               grid = (M/128), loops all N tiles internally.
// REDUCE=false: out[row,col] = acc + bias[col]; grid = (M/128, N/128).
// ---------------------------------------------------------------------------
constexpr int SMEM_BYTES = 2*128*40*2 * 2   // sAh + sAl
                         + 2*32*136*2 * 2   // sBh + sBl
                         + 128*2*4;         // red

template <int RPB_SHIFT, bool REDUCE>
__global__ void __launch_bounds__(256, 2) mma_gemm(
    const __nv_bfloat16* __restrict__ Ah, const __nv_bfloat16* __restrict__ Al,
    const __nv_bfloat16* __restrict__ Bh, const __nv_bfloat16* __restrict__ Bl,
    const float* __restrict__ EbOrBias,
    const float* __restrict__ wvec,
    const float* __restrict__ addsc,
    float* __restrict__ out,
    int N)
{
    extern __shared__ __align__(16) char smraw[];
    __nv_bfloat16* sAh = (__nv_bfloat16*)smraw;          // [2][128][40]
    __nv_bfloat16* sAl = sAh + 2 * 128 * 40;
    __nv_bfloat16* sBh = sAl + 2 * 128 * 40;             // [2][32][136]
    __nv_bfloat16* sBl = sBh + 2 * 32 * 136;
    float* red = (float*)(sBl + 2 * 32 * 136);           // [128][2]

    const int tid  = threadIdx.x;
    const int lane = tid & 31;
    const int wid  = tid >> 5;
    const int warp_m = wid & 3;
    const int warp_n = wid >> 2;
    const int lq = lane >> 2, lr = lane & 3;
    const int rb = blockIdx.x * 128;

    const uint32_t uAh = (uint32_t)__cvta_generic_to_shared(sAh);
    const uint32_t uAl = (uint32_t)__cvta_generic_to_shared(sAl);
    const uint32_t uBh = (uint32_t)__cvta_generic_to_shared(sBh);
    const uint32_t uBl = (uint32_t)__cvta_generic_to_shared(sBl);

    // staging chunk coords (2 x 16B chunks per thread per tile)
    int am[2], ak[2], bk[2], bn[2];
#pragma unroll
    for (int c = 0; c < 2; c++) {
        int cid = tid + c * 256;
        am[c] = cid >> 2;  ak[c] = (cid & 3) << 3;
        bk[c] = cid >> 4;  bn[c] = (cid & 15) << 3;
    }

    // ldmatrix per-lane address components
    const uint32_t a_frag_off =
        (uint32_t)(((warp_m * 32 + (lane & 15)) * 40 + ((lane & 16) >> 1)) * 2);
    const uint32_t b_frag_off =
        (uint32_t)(((lane & 15) * 136 + warp_n * 64 + ((lane & 16) >> 1)) * 2);

    float rs[2][2] = {{0.f, 0.f}, {0.f, 0.f}};
    const int ntiles = REDUCE ? (N >> 7) : 1;

    for (int nt = 0; nt < ntiles; nt++) {
        const int cb = REDUCE ? (nt << 7) : ((int)blockIdx.y << 7);

        float c[2][8][4] = {};

        auto stage = [&](int buf, int kt) {
            const int koff = kt << 5;
#pragma unroll
            for (int cc = 0; cc < 2; cc++) {
                size_t asrc = (size_t)(rb + am[cc]) * DDIM + koff + ak[cc];
                uint32_t adst = (uint32_t)(((buf * 128 + am[cc]) * 40 + ak[cc]) * 2);
                cp16(uAh + adst, Ah + asrc);
                cp16(uAl + adst, Al + asrc);
                size_t bsrc = (size_t)(koff + bk[cc]) * N + cb + bn[cc];
                uint32_t bdst = (uint32_t)(((buf * 32 + bk[cc]) * 136 + bn[cc]) * 2);
                cp16(uBh + bdst, Bh + bsrc);
                cp16(uBl + bdst, Bl + bsrc);
            }
        };

        stage(0, 0);
        cp_commit();

        for (int kt = 0; kt < DDIM / 32; kt++) {
            if (kt < DDIM / 32 - 1) stage((kt + 1) & 1, kt + 1);
            cp_commit();
            cp_wait1();
            __syncthreads();

            const int buf = kt & 1;
            const uint32_t abufoff = (uint32_t)(buf * 128 * 40 * 2);
            const uint32_t bbufoff = (uint32_t)(buf * 32 * 136 * 2);
#pragma unroll 1
            for (int rp = 0; rp < 3; rp++) {
                const uint32_t Abase = (rp < 2 ? uAh : uAl) + abufoff + a_frag_off;
                const uint32_t Bbase = (rp == 1 ? uBl : uBh) + bbufoff + b_frag_off;
#pragma unroll
                for (int kk = 0; kk < 32; kk += 16) {
                    unsigned a[2][4];
#pragma unroll
                    for (int mi = 0; mi < 2; mi++)
                        ldsm_x4(a[mi][0], a[mi][1], a[mi][2], a[mi][3],
                                Abase + (uint32_t)((mi * 16 * 40 + kk) * 2));
                    unsigned b[8][2];
#pragma unroll
                    for (int g = 0; g < 4; g++)
                        ldsm_x4_t(b[2*g][0], b[2*g][1], b[2*g+1][0], b[2*g+1][1],
                                  Bbase + (uint32_t)((kk * 136 + g * 16) * 2));
#pragma unroll
                    for (int mi = 0; mi < 2; mi++)
#pragma unroll
                        for (int ni = 0; ni < 8; ni++)
                            mma16816(c[mi][ni], a[mi], b[ni]);
                }
            }
            __syncthreads();
        }

        if (REDUCE) {
            // fused epilogue: relu(acc + Eb) . wvec
#pragma unroll
            for (int mi = 0; mi < 2; mi++) {
                int row0 = rb + warp_m * 32 + mi * 16 + lq;
                int row1 = row0 + 8;
                const float* Eb0 = EbOrBias + (size_t)(row0 >> RPB_SHIFT) * N;
                const float* Eb1 = EbOrBias + (size_t)(row1 >> RPB_SHIFT) * N;
#pragma unroll
                for (int ni = 0; ni < 8; ni++) {
                    int col = cb + warp_n * 64 + ni * 8 + lr * 2;
                    float2 e0 = *(const float2*)&Eb0[col];
                    float2 e1 = *(const float2*)&Eb1[col];
                    float2 wv = *(const float2*)&wvec[col];
                    rs[mi][0] += fmaxf(c[mi][ni][0] + e0.x, 0.f) * wv.x
                               + fmaxf(c[mi][ni][1] + e0.y, 0.f) * wv.y;
                    rs[mi][1] += fmaxf(c[mi][ni][2] + e1.x, 0.f) * wv.x
                               + fmaxf(c[mi][ni][3] + e1.y, 0.f) * wv.y;
                }
            }
        } else {
            // plain store epilogue: C = acc + bias
#pragma unroll
            for (int mi = 0; mi < 2; mi++) {
                int row0 = rb + warp_m * 32 + mi * 16 + lq;
                int row1 = row0 + 8;
#pragma unroll
                for (int ni = 0; ni < 8; ni++) {
                    int col = cb + warp_n * 64 + ni * 8 + lr * 2;
                    float2 bv = *(const float2*)&EbOrBias[col];
                    float2 o0, o1;
                    o0.x = c[mi][ni][0] + bv.x; o0.y = c[mi][ni][1] + bv.y;
                    o1.x = c[mi][ni][2] + bv.x; o1.y = c[mi][ni][3] + bv.y;
                    *(float2*)&out[(size_t)row0 * N + col] = o0;
                    *(float2*)&out[(size_t)row1 * N + col] = o1;
                }
            }
        }
    }

    if (REDUCE) {
        // reduce across the 4 lanes sharing each row
#pragma unroll
        for (int mi = 0; mi < 2; mi++)
#pragma unroll
            for (int h = 0; h < 2; h++) {
                float s = rs[mi][h];
                s += __shfl_xor_sync(0xffffffffu, s, 1);
                s += __shfl_xor_sync(0xffffffffu, s, 2);
                if (lr == 0) red[(warp_m * 32 + mi * 16 + h * 8 + lq) * 2 + warp_n] = s;
            }
        __syncthreads();
        if (tid < 128) {
            float addv = addsc ? *addsc : 0.f;
            out[rb + tid] = red[tid * 2 + 0] + red[tid * 2 + 1] + addv;
        }
    }
}

// ---------------------------------------------------------------------------
// K4: per-b softmax over T=32 then x_hat = sum_t alpha_t * X[b,t,:], split out
// ---------------------------------------------------------------------------
__global__ void softmax_xhat_split_kernel(const float* __restrict__ e,
                                          const float* __restrict__ X,
                                          __nv_bfloat16* __restrict__ xh,
                                          __nv_bfloat16* __restrict__ xl)
{
    int b = blockIdx.x;
    __shared__ float alpha[TDIM];
    int tid = threadIdx.x;   // 128 threads
    if (tid < 32) {
        float v = e[b * TDIM + tid];
        float m = v;
#pragma unroll
        for (int off = 16; off >= 1; off >>= 1)
            m = fmaxf(m, __shfl_xor_sync(0xffffffffu, m, off));
        float ex = __expf(v - m);
        float s = ex;
#pragma unroll
        for (int off = 16; off >= 1; off >>= 1)
            s += __shfl_xor_sync(0xffffffffu, s, off);
        alpha[tid] = ex / s;
    }
    __syncthreads();
    const float* Xb = X + (size_t)b * TDIM * DDIM;
#pragma unroll 1
    for (int d = tid; d < DDIM; d += 128) {
        float s = 0.f;
#pragma unroll
        for (int t = 0; t < TDIM; t++) s += alpha[t] * Xb[t * DDIM + d];
        __nv_bfloat16 hh = __float2bfloat16(s);
        xh[(size_t)b * DDIM + d] = hh;
        xl[(size_t)b * DDIM + d] = __float2bfloat16(s - __bfloat162float(hh));
    }
}

// ---------------------------------------------------------------------------
extern "C" void kernel_launch(void* const* d_in, const int* in_sizes, int n_in,
                              void* d_out, int out_size)
{
    const float* X  = (const float*)d_in[0];
    const float* G  = (const float*)d_in[1];
    const float* W1 = (const float*)d_in[2];
    const float* b1 = (const float*)d_in[3];
    const float* w2 = (const float*)d_in[4];
    // d_in[5] = b2: softmax shift-invariant, unused
    const float* M1 = (const float*)d_in[6];
    const float* c1 = (const float*)d_in[7];
    const float* m2 = (const float*)d_in[8];
    const float* c2 = (const float*)d_in[9];
    float* out = (float*)d_out;

    float *E1, *E2, *ebuf;
    cudaGetSymbolAddress((void**)&E1,   E1_buf);
    cudaGetSymbolAddress((void**)&E2,   E2_buf);
    cudaGetSymbolAddress((void**)&ebuf, e_buf);

    __nv_bfloat16 *Xh, *Xl, *Gh, *Gl, *W1h, *W1l, *M1h, *M1l, *ghh, *ghl, *xhh, *xhl;
    cudaGetSymbolAddress((void**)&Xh,  Xh_buf);
    cudaGetSymbolAddress((void**)&Xl,  Xl_buf);
    cudaGetSymbolAddress((void**)&Gh,  Gh_buf);
    cudaGetSymbolAddress((void**)&Gl,  Gl_buf);
    cudaGetSymbolAddress((void**)&W1h, W1h_buf);
    cudaGetSymbolAddress((void**)&W1l, W1l_buf);
    cudaGetSymbolAddress((void**)&M1h, M1h_buf);
    cudaGetSymbolAddress((void**)&M1l, M1l_buf);
    cudaGetSymbolAddress((void**)&ghh, ghh_buf);
    cudaGetSymbolAddress((void**)&ghl, ghl_buf);
    cudaGetSymbolAddress((void**)&xhh, xhh_buf);
    cudaGetSymbolAddress((void**)&xhl, xhl_buf);

    cudaFuncSetAttribute(mma_gemm<5, true>,
                         cudaFuncAttributeMaxDynamicSharedMemorySize, SMEM_BYTES);
    cudaFuncSetAttribute(mma_gemm<4, true>,
                         cudaFuncAttributeMaxDynamicSharedMemorySize, SMEM_BYTES);
    cudaFuncSetAttribute(mma_gemm<0, false>,
                         cudaFuncAttributeMaxDynamicSharedMemorySize, SMEM_BYTES);

    // split-bf16 conversions
    split_bf16_kernel<<<(BDIM * TDIM * DDIM / 4) / 256, 256>>>(X, Xh, Xl);
    split_bf16_kernel<<<(BDIM * KDIM * DDIM / 4) / 256, 256>>>(G, Gh, Gl);
    split_bf16_kernel<<<(2 * DDIM * HDIM / 4) / 256, 256>>>(W1, W1h, W1l);
    split_bf16_kernel<<<(2 * DDIM * H2DIM / 4) / 256, 256>>>(M1, M1h, M1l);

    // K1: g_hat (split output)
    gmean_split_kernel<<<(BDIM * DDIM) / 256, 256>>>(G, ghh, ghl);

    // K2: E1 = g_hat @ W1[:512] + b1   (4096 x 1024)
    mma_gemm<0, false><<<dim3(BDIM / 128, HDIM / 128), 256, SMEM_BYTES>>>(
        ghh, ghl, W1h, W1l, b1, nullptr, nullptr, E1, HDIM);

    // K3: e[b,t] = sum_h relu( X@W1[512:] + E1 ) * w2   (M = 131072)
    mma_gemm<5, true><<<(BDIM * TDIM) / 128, 256, SMEM_BYTES>>>(
        Xh, Xl, W1h + (size_t)DDIM * HDIM, W1l + (size_t)DDIM * HDIM,
        E1, w2, nullptr, ebuf, HDIM);

    // K4: softmax over T + x_hat (split output)
    softmax_xhat_split_kernel<<<BDIM, 128>>>(ebuf, X, xhh, xhl);

    // K5: E2 = x_hat @ M1[:512] + c1   (4096 x 2048)
    mma_gemm<0, false><<<dim3(BDIM / 128, H2DIM / 128), 256, SMEM_BYTES>>>(
        xhh, xhl, M1h, M1l, c1, nullptr, nullptr, E2, H2DIM);

    // K6: logits[b,k] = sum_j relu( G@M1[512:] + E2 ) * m2 + c2   (M = 65536)
    mma_gemm<4, true><<<(BDIM * KDIM) / 128, 256, SMEM_BYTES>>>(
        Gh, Gl, M1h + (size_t)DDIM * H2DIM, M1l + (size_t)DDIM * H2DIM,
        E2, m2, c2, out, H2DIM);
}

// round 7
// speedup vs baseline: 3.1791x; 1.0318x over previous
#include <cuda_runtime.h>
#include <cuda_bf16.h>
#include <cstdint>

// Problem constants
#define BDIM  4096
#define TDIM  32
#define KDIM  16
#define DDIM  512
#define HDIM  1024   // = 2*D
#define H2DIM 2048   // = 2*H

// NOTE: harness PTX target is compute_103 (no 'a') -> tcgen05/TMEM are
// rejected by ptxas. Legacy mma.sync HMMA is the only tensor path here.

// ---------------------------------------------------------------------------
// Scratch (device globals: allocation-free rule)
// ---------------------------------------------------------------------------
__device__ float E1_buf[BDIM * HDIM];
__device__ float E2_buf[BDIM * H2DIM];
__device__ float e_buf[BDIM * TDIM];

__device__ __nv_bfloat16 Xh_buf[BDIM * TDIM * DDIM];
__device__ __nv_bfloat16 Xl_buf[BDIM * TDIM * DDIM];
__device__ __nv_bfloat16 Gh_buf[BDIM * KDIM * DDIM];
__device__ __nv_bfloat16 Gl_buf[BDIM * KDIM * DDIM];
__device__ __nv_bfloat16 W1h_buf[2 * DDIM * HDIM];   // full W1 (1024 x 1024)
__device__ __nv_bfloat16 W1l_buf[2 * DDIM * HDIM];
__device__ __nv_bfloat16 M1h_buf[2 * DDIM * H2DIM];  // full M1 (1024 x 2048)
__device__ __nv_bfloat16 M1l_buf[2 * DDIM * H2DIM];
__device__ __nv_bfloat16 ghh_buf[BDIM * DDIM];
__device__ __nv_bfloat16 ghl_buf[BDIM * DDIM];
__device__ __nv_bfloat16 xhh_buf[BDIM * DDIM];
__device__ __nv_bfloat16 xhl_buf[BDIM * DDIM];

// ---------------------------------------------------------------------------
// PTX helpers
// ---------------------------------------------------------------------------
__device__ __forceinline__ void cp16(uint32_t dst, const void* src) {
    asm volatile("cp.async.cg.shared.global [%0], [%1], 16;\n"
                 :: "r"(dst), "l"(src) : "memory");
}
__device__ __forceinline__ void cp_commit() {
    asm volatile("cp.async.commit_group;\n" ::: "memory");
}
__device__ __forceinline__ void cp_wait1() {
    asm volatile("cp.async.wait_group 1;\n" ::: "memory");
}
__device__ __forceinline__ void ldsm_x4(unsigned& d0, unsigned& d1, unsigned& d2,
                                        unsigned& d3, uint32_t addr) {
    asm volatile("ldmatrix.sync.aligned.m8n8.x4.shared.b16 {%0,%1,%2,%3}, [%4];\n"
                 : "=r"(d0), "=r"(d1), "=r"(d2), "=r"(d3) : "r"(addr));
}
__device__ __forceinline__ void ldsm_x4_t(unsigned& d0, unsigned& d1, unsigned& d2,
                                          unsigned& d3, uint32_t addr) {
    asm volatile("ldmatrix.sync.aligned.m8n8.x4.trans.shared.b16 {%0,%1,%2,%3}, [%4];\n"
                 : "=r"(d0), "=r"(d1), "=r"(d2), "=r"(d3) : "r"(addr));
}
__device__ __forceinline__ void mma16816(float c[4], const unsigned a[4], const unsigned b[2]) {
    asm volatile(
        "mma.sync.aligned.m16n8k16.row.col.f32.bf16.bf16.f32 "
        "{%0,%1,%2,%3}, {%4,%5,%6,%7}, {%8,%9}, {%0,%1,%2,%3};\n"
        : "+f"(c[0]), "+f"(c[1]), "+f"(c[2]), "+f"(c[3])
        : "r"(a[0]), "r"(a[1]), "r"(a[2]), "r"(a[3]), "r"(b[0]), "r"(b[1]));
}

// ---------------------------------------------------------------------------
// split: hi = bf16(x); lo = bf16(x - hi)
// ---------------------------------------------------------------------------
__global__ void split_bf16_kernel(const float* __restrict__ src,
                                  __nv_bfloat16* __restrict__ hi,
                                  __nv_bfloat16* __restrict__ lo)
{
    int i = blockIdx.x * blockDim.x + threadIdx.x;
    float4 v = ((const float4*)src)[i];
    __nv_bfloat16 h[4], l[4];
    float x;
    x = v.x; h[0] = __float2bfloat16(x); l[0] = __float2bfloat16(x - __bfloat162float(h[0]));
    x = v.y; h[1] = __float2bfloat16(x); l[1] = __float2bfloat16(x - __bfloat162float(h[1]));
    x = v.z; h[2] = __float2bfloat16(x); l[2] = __float2bfloat16(x - __bfloat162float(h[2]));
    x = v.w; h[3] = __float2bfloat16(x); l[3] = __float2bfloat16(x - __bfloat162float(h[3]));
    ((uint2*)hi)[i] = *(uint2*)h;
    ((uint2*)lo)[i] = *(uint2*)l;
}

// ---------------------------------------------------------------------------
// K1: g_hat = mean_k G, written directly as split-bf16
// ---------------------------------------------------------------------------
__global__ void gmean_split_kernel(const float* __restrict__ G,
                                   __nv_bfloat16* __restrict__ h,
                                   __nv_bfloat16* __restrict__ l)
{
    int idx = blockIdx.x * blockDim.x + threadIdx.x;   // over B*D
    int b = idx >> 9;
    int d = idx & 511;
    const float* g = G + (size_t)b * KDIM * DDIM + d;
    float s = 0.f;
#pragma unroll
    for (int k = 0; k < KDIM; k++) s += g[k * DDIM];
    s *= (1.0f / KDIM);
    __nv_bfloat16 hh = __float2bfloat16(s);
    h[idx] = hh;
    l[idx] = __float2bfloat16(s - __bfloat162float(hh));
}

// ---------------------------------------------------------------------------
// Tensor-core split-bf16 GEMM, BM=128, BN=128, BK=32, 8 warps (4m x 2n).
// Logical K = 1536: AhBh + AhBl + AlBh, with register-reuse pass ordering:
//   load Ah,Bh -> pass0; stream Bl vs live Ah -> pass1; load Al vs live Bh -> pass2.
// REDUCE=true : out[row] = sum_n relu(acc + Eb[row>>RPB_SHIFT, n]) * wvec[n] (+sc)
//               grid = (M/128), loops all N tiles internally.
// REDUCE=false: out[row,col] = acc + bias[col]; grid = (M/128, N/128).
// ---------------------------------------------------------------------------
constexpr int SMEM_BYTES = 2*128*40*2 * 2   // sAh + sAl
                         + 2*32*136*2 * 2   // sBh + sBl
                         + 128*2*4;         // red

template <int RPB_SHIFT, bool REDUCE>
__global__ void __launch_bounds__(256, 2) mma_gemm(
    const __nv_bfloat16* __restrict__ Ah, const __nv_bfloat16* __restrict__ Al,
    const __nv_bfloat16* __restrict__ Bh, const __nv_bfloat16* __restrict__ Bl,
    const float* __restrict__ EbOrBias,
    const float* __restrict__ wvec,
    const float* __restrict__ addsc,
    float* __restrict__ out,
    int N)
{
    extern __shared__ __align__(16) char smraw[];
    __nv_bfloat16* sAh = (__nv_bfloat16*)smraw;          // [2][128][40]
    __nv_bfloat16* sAl = sAh + 2 * 128 * 40;
    __nv_bfloat16* sBh = sAl + 2 * 128 * 40;             // [2][32][136]
    __nv_bfloat16* sBl = sBh + 2 * 32 * 136;
    float* red = (float*)(sBl + 2 * 32 * 136);           // [128][2]

    const int tid  = threadIdx.x;
    const int lane = tid & 31;
    const int wid  = tid >> 5;
    const int warp_m = wid & 3;
    const int warp_n = wid >> 2;
    const int lq = lane >> 2, lr = lane & 3;
    const int rb = blockIdx.x * 128;

    const uint32_t uAh = (uint32_t)__cvta_generic_to_shared(sAh);
    const uint32_t uAl = (uint32_t)__cvta_generic_to_shared(sAl);
    const uint32_t uBh = (uint32_t)__cvta_generic_to_shared(sBh);
    const uint32_t uBl = (uint32_t)__cvta_generic_to_shared(sBl);

    // staging chunk coords (2 x 16B chunks per thread per tile)
    int am[2], ak[2], bk[2], bn[2];
#pragma unroll
    for (int c = 0; c < 2; c++) {
        int cid = tid + c * 256;
        am[c] = cid >> 2;  ak[c] = (cid & 3) << 3;
        bk[c] = cid >> 4;  bn[c] = (cid & 15) << 3;
    }

    // ldmatrix per-lane address components
    const uint32_t a_frag_off =
        (uint32_t)(((warp_m * 32 + (lane & 15)) * 40 + ((lane & 16) >> 1)) * 2);
    const uint32_t b_frag_off =
        (uint32_t)(((lane & 15) * 136 + warp_n * 64 + ((lane & 16) >> 1)) * 2);

    float rs[2][2] = {{0.f, 0.f}, {0.f, 0.f}};
    const int ntiles = REDUCE ? (N >> 7) : 1;

    for (int nt = 0; nt < ntiles; nt++) {
        const int cb = REDUCE ? (nt << 7) : ((int)blockIdx.y << 7);

        float c[2][8][4] = {};

        auto stage = [&](int buf, int kt) {
            const int koff = kt << 5;
#pragma unroll
            for (int cc = 0; cc < 2; cc++) {
                size_t asrc = (size_t)(rb + am[cc]) * DDIM + koff + ak[cc];
                uint32_t adst = (uint32_t)(((buf * 128 + am[cc]) * 40 + ak[cc]) * 2);
                cp16(uAh + adst, Ah + asrc);
                cp16(uAl + adst, Al + asrc);
                size_t bsrc = (size_t)(koff + bk[cc]) * N + cb + bn[cc];
                uint32_t bdst = (uint32_t)(((buf * 32 + bk[cc]) * 136 + bn[cc]) * 2);
                cp16(uBh + bdst, Bh + bsrc);
                cp16(uBl + bdst, Bl + bsrc);
            }
        };

        stage(0, 0);
        cp_commit();

        for (int kt = 0; kt < DDIM / 32; kt++) {
            if (kt < DDIM / 32 - 1) stage((kt + 1) & 1, kt + 1);
            cp_commit();
            cp_wait1();
            __syncthreads();

            const int buf = kt & 1;
            const uint32_t abufoff = (uint32_t)(buf * 128 * 40 * 2);
            const uint32_t bbufoff = (uint32_t)(buf * 32 * 136 * 2);
            const uint32_t Ahb = uAh + abufoff + a_frag_off;
            const uint32_t Alb = uAl + abufoff + a_frag_off;
            const uint32_t Bhb = uBh + bbufoff + b_frag_off;
            const uint32_t Blb = uBl + bbufoff + b_frag_off;

#pragma unroll
            for (int kk = 0; kk < 32; kk += 16) {
                // --- load Ah + Bh fragments once ---
                unsigned ah[2][4], al[2][4], bh[8][2];
#pragma unroll
                for (int mi = 0; mi < 2; mi++)
                    ldsm_x4(ah[mi][0], ah[mi][1], ah[mi][2], ah[mi][3],
                            Ahb + (uint32_t)((mi * 16 * 40 + kk) * 2));
#pragma unroll
                for (int g = 0; g < 4; g++)
                    ldsm_x4_t(bh[2*g][0], bh[2*g][1], bh[2*g+1][0], bh[2*g+1][1],
                              Bhb + (uint32_t)((kk * 136 + g * 16) * 2));

                // pass0: Ah * Bh
#pragma unroll
                for (int mi = 0; mi < 2; mi++)
#pragma unroll
                    for (int ni = 0; ni < 8; ni++)
                        mma16816(c[mi][ni], ah[mi], bh[ni]);

                // pass1: Ah * Bl  (stream Bl 2 ni at a time)
#pragma unroll
                for (int g = 0; g < 4; g++) {
                    unsigned t[4];
                    ldsm_x4_t(t[0], t[1], t[2], t[3],
                              Blb + (uint32_t)((kk * 136 + g * 16) * 2));
                    unsigned b0[2] = {t[0], t[1]}, b1[2] = {t[2], t[3]};
#pragma unroll
                    for (int mi = 0; mi < 2; mi++) {
                        mma16816(c[mi][2*g],   ah[mi], b0);
                        mma16816(c[mi][2*g+1], ah[mi], b1);
                    }
                }

                // pass2: Al * Bh  (Bh still live)
#pragma unroll
                for (int mi = 0; mi < 2; mi++)
                    ldsm_x4(al[mi][0], al[mi][1], al[mi][2], al[mi][3],
                            Alb + (uint32_t)((mi * 16 * 40 + kk) * 2));
#pragma unroll
                for (int mi = 0; mi < 2; mi++)
#pragma unroll
                    for (int ni = 0; ni < 8; ni++)
                        mma16816(c[mi][ni], al[mi], bh[ni]);
            }
            __syncthreads();
        }

        if (REDUCE) {
            // fused epilogue: relu(acc + Eb) . wvec
#pragma unroll
            for (int mi = 0; mi < 2; mi++) {
                int row0 = rb + warp_m * 32 + mi * 16 + lq;
                int row1 = row0 + 8;
                const float* Eb0 = EbOrBias + (size_t)(row0 >> RPB_SHIFT) * N;
                const float* Eb1 = EbOrBias + (size_t)(row1 >> RPB_SHIFT) * N;
#pragma unroll
                for (int ni = 0; ni < 8; ni++) {
                    int col = cb + warp_n * 64 + ni * 8 + lr * 2;
                    float2 e0 = *(const float2*)&Eb0[col];
                    float2 e1 = *(const float2*)&Eb1[col];
                    float2 wv = *(const float2*)&wvec[col];
                    rs[mi][0] += fmaxf(c[mi][ni][0] + e0.x, 0.f) * wv.x
                               + fmaxf(c[mi][ni][1] + e0.y, 0.f) * wv.y;
                    rs[mi][1] += fmaxf(c[mi][ni][2] + e1.x, 0.f) * wv.x
                               + fmaxf(c[mi][ni][3] + e1.y, 0.f) * wv.y;
                }
            }
        } else {
            // plain store epilogue: C = acc + bias
#pragma unroll
            for (int mi = 0; mi < 2; mi++) {
                int row0 = rb + warp_m * 32 + mi * 16 + lq;
                int row1 = row0 + 8;
#pragma unroll
                for (int ni = 0; ni < 8; ni++) {
                    int col = cb + warp_n * 64 + ni * 8 + lr * 2;
                    float2 bv = *(const float2*)&EbOrBias[col];
                    float2 o0, o1;
                    o0.x = c[mi][ni][0] + bv.x; o0.y = c[mi][ni][1] + bv.y;
                    o1.x = c[mi][ni][2] + bv.x; o1.y = c[mi][ni][3] + bv.y;
                    *(float2*)&out[(size_t)row0 * N + col] = o0;
                    *(float2*)&out[(size_t)row1 * N + col] = o1;
                }
            }
        }
    }

    if (REDUCE) {
        // reduce across the 4 lanes sharing each row
#pragma unroll
        for (int mi = 0; mi < 2; mi++)
#pragma unroll
            for (int h = 0; h < 2; h++) {
                float s = rs[mi][h];
                s += __shfl_xor_sync(0xffffffffu, s, 1);
                s += __shfl_xor_sync(0xffffffffu, s, 2);
                if (lr == 0) red[(warp_m * 32 + mi * 16 + h * 8 + lq) * 2 + warp_n] = s;
            }
        __syncthreads();
        if (tid < 128) {
            float addv = addsc ? *addsc : 0.f;
            out[rb + tid] = red[tid * 2 + 0] + red[tid * 2 + 1] + addv;
        }
    }
}

// ---------------------------------------------------------------------------
// K4: per-b softmax over T=32 then x_hat = sum_t alpha_t * X[b,t,:], split out
// ---------------------------------------------------------------------------
__global__ void softmax_xhat_split_kernel(const float* __restrict__ e,
                                          const float* __restrict__ X,
                                          __nv_bfloat16* __restrict__ xh,
                                          __nv_bfloat16* __restrict__ xl)
{
    int b = blockIdx.x;
    __shared__ float alpha[TDIM];
    int tid = threadIdx.x;   // 128 threads
    if (tid < 32) {
        float v = e[b * TDIM + tid];
        float m = v;
#pragma unroll
        for (int off = 16; off >= 1; off >>= 1)
            m = fmaxf(m, __shfl_xor_sync(0xffffffffu, m, off));
        float ex = __expf(v - m);
        float s = ex;
#pragma unroll
        for (int off = 16; off >= 1; off >>= 1)
            s += __shfl_xor_sync(0xffffffffu, s, off);
        alpha[tid] = ex / s;
    }
    __syncthreads();
    const float* Xb = X + (size_t)b * TDIM * DDIM;
#pragma unroll 1
    for (int d = tid; d < DDIM; d += 128) {
        float s = 0.f;
#pragma unroll
        for (int t = 0; t < TDIM; t++) s += alpha[t] * Xb[t * DDIM + d];
        __nv_bfloat16 hh = __float2bfloat16(s);
        xh[(size_t)b * DDIM + d] = hh;
        xl[(size_t)b * DDIM + d] = __float2bfloat16(s - __bfloat162float(hh));
    }
}

// ---------------------------------------------------------------------------
extern "C" void kernel_launch(void* const* d_in, const int* in_sizes, int n_in,
                              void* d_out, int out_size)
{
    const float* X  = (const float*)d_in[0];
    const float* G  = (const float*)d_in[1];
    const float* W1 = (const float*)d_in[2];
    const float* b1 = (const float*)d_in[3];
    const float* w2 = (const float*)d_in[4];
    // d_in[5] = b2: softmax shift-invariant, unused
    const float* M1 = (const float*)d_in[6];
    const float* c1 = (const float*)d_in[7];
    const float* m2 = (const float*)d_in[8];
    const float* c2 = (const float*)d_in[9];
    float* out = (float*)d_out;

    float *E1, *E2, *ebuf;
    cudaGetSymbolAddress((void**)&E1,   E1_buf);
    cudaGetSymbolAddress((void**)&E2,   E2_buf);
    cudaGetSymbolAddress((void**)&ebuf, e_buf);

    __nv_bfloat16 *Xh, *Xl, *Gh, *Gl, *W1h, *W1l, *M1h, *M1l, *ghh, *ghl, *xhh, *xhl;
    cudaGetSymbolAddress((void**)&Xh,  Xh_buf);
    cudaGetSymbolAddress((void**)&Xl,  Xl_buf);
    cudaGetSymbolAddress((void**)&Gh,  Gh_buf);
    cudaGetSymbolAddress((void**)&Gl,  Gl_buf);
    cudaGetSymbolAddress((void**)&W1h, W1h_buf);
    cudaGetSymbolAddress((void**)&W1l, W1l_buf);
    cudaGetSymbolAddress((void**)&M1h, M1h_buf);
    cudaGetSymbolAddress((void**)&M1l, M1l_buf);
    cudaGetSymbolAddress((void**)&ghh, ghh_buf);
    cudaGetSymbolAddress((void**)&ghl, ghl_buf);
    cudaGetSymbolAddress((void**)&xhh, xhh_buf);
    cudaGetSymbolAddress((void**)&xhl, xhl_buf);

    cudaFuncSetAttribute(mma_gemm<5, true>,
                         cudaFuncAttributeMaxDynamicSharedMemorySize, SMEM_BYTES);
    cudaFuncSetAttribute(mma_gemm<4, true>,
                         cudaFuncAttributeMaxDynamicSharedMemorySize, SMEM_BYTES);
    cudaFuncSetAttribute(mma_gemm<0, false>,
                         cudaFuncAttributeMaxDynamicSharedMemorySize, SMEM_BYTES);

    // split-bf16 conversions
    split_bf16_kernel<<<(BDIM * TDIM * DDIM / 4) / 256, 256>>>(X, Xh, Xl);
    split_bf16_kernel<<<(BDIM * KDIM * DDIM / 4) / 256, 256>>>(G, Gh, Gl);
    split_bf16_kernel<<<(2 * DDIM * HDIM / 4) / 256, 256>>>(W1, W1h, W1l);
    split_bf16_kernel<<<(2 * DDIM * H2DIM / 4) / 256, 256>>>(M1, M1h, M1l);

    // K1: g_hat (split output)
    gmean_split_kernel<<<(BDIM * DDIM) / 256, 256>>>(G, ghh, ghl);

    // K2: E1 = g_hat @ W1[:512] + b1   (4096 x 1024)
    mma_gemm<0, false><<<dim3(BDIM / 128, HDIM / 128), 256, SMEM_BYTES>>>(
        ghh, ghl, W1h, W1l, b1, nullptr, nullptr, E1, HDIM);

    // K3: e[b,t] = sum_h relu( X@W1[512:] + E1 ) * w2   (M = 131072)
    mma_gemm<5, true><<<(BDIM * TDIM) / 128, 256, SMEM_BYTES>>>(
        Xh, Xl, W1h + (size_t)DDIM * HDIM, W1l + (size_t)DDIM * HDIM,
        E1, w2, nullptr, ebuf, HDIM);

    // K4: softmax over T + x_hat (split output)
    softmax_xhat_split_kernel<<<BDIM, 128>>>(ebuf, X, xhh, xhl);

    // K5: E2 = x_hat @ M1[:512] + c1   (4096 x 2048)
    mma_gemm<0, false><<<dim3(BDIM / 128, H2DIM / 128), 256, SMEM_BYTES>>>(
        xhh, xhl, M1h, M1l, c1, nullptr, nullptr, E2, H2DIM);

    // K6: logits[b,k] = sum_j relu( G@M1[512:] + E2 ) * m2 + c2   (M = 65536)
    mma_gemm<4, true><<<(BDIM * KDIM) / 128, 256, SMEM_BYTES>>>(
        Gh, Gl, M1h + (size_t)DDIM * H2DIM, M1l + (size_t)DDIM * H2DIM,
        E2, m2, c2, out, H2DIM);
}

// round 8
// speedup vs baseline: 4.1340x; 1.3004x over previous
#include <cuda_runtime.h>
#include <cuda_fp16.h>
#include <cstdint>

// Problem constants
#define BDIM  4096
#define TDIM  32
#define KDIM  16
#define DDIM  512
#define HDIM  1024   // = 2*D
#define H2DIM 2048   // = 2*H

// NOTE: harness PTX target is compute_103 (no 'a') -> tcgen05/TMEM rejected.
// Legacy mma.sync HMMA is the tensor path. fp16-split (hi/lo) operands:
//   A = Ah + Al (22 mantissa bits), B = Bh (11 bits).
//   Big GEMMs: 2 passes (AhBh + AlBh), err ~2.8e-4 pre-relu -> ~1e-4 logits.
//   Small GEMMs (E1/E2): 3 passes (+ AhBl), err ~2^-22.

// ---------------------------------------------------------------------------
// Scratch (device globals: allocation-free rule)
// ---------------------------------------------------------------------------
__device__ float E1_buf[BDIM * HDIM];
__device__ float E2_buf[BDIM * H2DIM];
__device__ float e_buf[BDIM * TDIM];

__device__ __half Xh_buf[BDIM * TDIM * DDIM];
__device__ __half Xl_buf[BDIM * TDIM * DDIM];
__device__ __half Gh_buf[BDIM * KDIM * DDIM];
__device__ __half Gl_buf[BDIM * KDIM * DDIM];
__device__ __half W1h_buf[2 * DDIM * HDIM];   // full W1 (1024 x 1024)
__device__ __half W1l_buf[2 * DDIM * HDIM];
__device__ __half M1h_buf[2 * DDIM * H2DIM];  // full M1 (1024 x 2048)
__device__ __half M1l_buf[2 * DDIM * H2DIM];
__device__ __half ghh_buf[BDIM * DDIM];
__device__ __half ghl_buf[BDIM * DDIM];
__device__ __half xhh_buf[BDIM * DDIM];
__device__ __half xhl_buf[BDIM * DDIM];

// ---------------------------------------------------------------------------
// PTX helpers
// ---------------------------------------------------------------------------
__device__ __forceinline__ void cp16(uint32_t dst, const void* src) {
    asm volatile("cp.async.cg.shared.global [%0], [%1], 16;\n"
                 :: "r"(dst), "l"(src) : "memory");
}
__device__ __forceinline__ void cp_commit() {
    asm volatile("cp.async.commit_group;\n" ::: "memory");
}
__device__ __forceinline__ void cp_wait1() {
    asm volatile("cp.async.wait_group 1;\n" ::: "memory");
}
__device__ __forceinline__ void ldsm_x4(unsigned& d0, unsigned& d1, unsigned& d2,
                                        unsigned& d3, uint32_t addr) {
    asm volatile("ldmatrix.sync.aligned.m8n8.x4.shared.b16 {%0,%1,%2,%3}, [%4];\n"
                 : "=r"(d0), "=r"(d1), "=r"(d2), "=r"(d3) : "r"(addr));
}
__device__ __forceinline__ void ldsm_x4_t(unsigned& d0, unsigned& d1, unsigned& d2,
                                          unsigned& d3, uint32_t addr) {
    asm volatile("ldmatrix.sync.aligned.m8n8.x4.trans.shared.b16 {%0,%1,%2,%3}, [%4];\n"
                 : "=r"(d0), "=r"(d1), "=r"(d2), "=r"(d3) : "r"(addr));
}
__device__ __forceinline__ void mma16816(float c[4], const unsigned a[4], const unsigned b[2]) {
    asm volatile(
        "mma.sync.aligned.m16n8k16.row.col.f32.f16.f16.f32 "
        "{%0,%1,%2,%3}, {%4,%5,%6,%7}, {%8,%9}, {%0,%1,%2,%3};\n"
        : "+f"(c[0]), "+f"(c[1]), "+f"(c[2]), "+f"(c[3])
        : "r"(a[0]), "r"(a[1]), "r"(a[2]), "r"(a[3]), "r"(b[0]), "r"(b[1]));
}

// ---------------------------------------------------------------------------
// split: hi = fp16(x); lo = fp16(x - hi)
// ---------------------------------------------------------------------------
__global__ void split_fp16_kernel(const float* __restrict__ src,
                                  __half* __restrict__ hi,
                                  __half* __restrict__ lo)
{
    int i = blockIdx.x * blockDim.x + threadIdx.x;
    float4 v = ((const float4*)src)[i];
    __half h[4], l[4];
    float x;
    x = v.x; h[0] = __float2half_rn(x); l[0] = __float2half_rn(x - __half2float(h[0]));
    x = v.y; h[1] = __float2half_rn(x); l[1] = __float2half_rn(x - __half2float(h[1]));
    x = v.z; h[2] = __float2half_rn(x); l[2] = __float2half_rn(x - __half2float(h[2]));
    x = v.w; h[3] = __float2half_rn(x); l[3] = __float2half_rn(x - __half2float(h[3]));
    ((uint2*)hi)[i] = *(uint2*)h;
    ((uint2*)lo)[i] = *(uint2*)l;
}

// ---------------------------------------------------------------------------
// K1: g_hat = mean_k G, split-fp16 output
// ---------------------------------------------------------------------------
__global__ void gmean_split_kernel(const float* __restrict__ G,
                                   __half* __restrict__ h,
                                   __half* __restrict__ l)
{
    int idx = blockIdx.x * blockDim.x + threadIdx.x;   // over B*D
    int b = idx >> 9;
    int d = idx & 511;
    const float* g = G + (size_t)b * KDIM * DDIM + d;
    float s = 0.f;
#pragma unroll
    for (int k = 0; k < KDIM; k++) s += g[k * DDIM];
    s *= (1.0f / KDIM);
    __half hh = __float2half_rn(s);
    h[idx] = hh;
    l[idx] = __float2half_rn(s - __half2float(hh));
}

// ---------------------------------------------------------------------------
// Tensor-core split-fp16 GEMM, BM=128, BN=128, BK=32, 8 warps (4m x 2n).
// NPASS=2: AhBh + AlBh.   NPASS=3: + AhBl.
// REDUCE=true : out[row] = sum_n relu(acc + Eb[row>>RPB_SHIFT, n]) * wvec[n] (+sc)
//               grid = (M/128), loops all N tiles internally.
// REDUCE=false: out[row,col] = acc + bias[col]; grid = (M/128, N/128).
// ---------------------------------------------------------------------------
constexpr int SMEM_BYTES = 2*128*40*2 * 2   // sAh + sAl
                         + 2*32*136*2 * 2   // sBh + sBl
                         + 128*2*4;         // red

template <int RPB_SHIFT, bool REDUCE, int NPASS>
__global__ void __launch_bounds__(256, 2) mma_gemm(
    const __half* __restrict__ Ah, const __half* __restrict__ Al,
    const __half* __restrict__ Bh, const __half* __restrict__ Bl,
    const float* __restrict__ EbOrBias,
    const float* __restrict__ wvec,
    const float* __restrict__ addsc,
    float* __restrict__ out,
    int N)
{
    extern __shared__ __align__(16) char smraw[];
    __half* sAh = (__half*)smraw;                // [2][128][40]
    __half* sAl = sAh + 2 * 128 * 40;
    __half* sBh = sAl + 2 * 128 * 40;            // [2][32][136]
    __half* sBl = sBh + 2 * 32 * 136;
    float* red = (float*)(sBl + 2 * 32 * 136);   // [128][2]

    const int tid  = threadIdx.x;
    const int lane = tid & 31;
    const int wid  = tid >> 5;
    const int warp_m = wid & 3;
    const int warp_n = wid >> 2;
    const int lq = lane >> 2, lr = lane & 3;
    const int rb = blockIdx.x * 128;

    const uint32_t uAh = (uint32_t)__cvta_generic_to_shared(sAh);
    const uint32_t uAl = (uint32_t)__cvta_generic_to_shared(sAl);
    const uint32_t uBh = (uint32_t)__cvta_generic_to_shared(sBh);
    const uint32_t uBl = (uint32_t)__cvta_generic_to_shared(sBl);

    // staging chunk coords (2 x 16B chunks per thread per tile)
    int am[2], ak[2], bk[2], bn[2];
#pragma unroll
    for (int c = 0; c < 2; c++) {
        int cid = tid + c * 256;
        am[c] = cid >> 2;  ak[c] = (cid & 3) << 3;
        bk[c] = cid >> 4;  bn[c] = (cid & 15) << 3;
    }

    // ldmatrix per-lane address components
    const uint32_t a_frag_off =
        (uint32_t)(((warp_m * 32 + (lane & 15)) * 40 + ((lane & 16) >> 1)) * 2);
    const uint32_t b_frag_off =
        (uint32_t)(((lane & 15) * 136 + warp_n * 64 + ((lane & 16) >> 1)) * 2);

    float rs[2][2] = {{0.f, 0.f}, {0.f, 0.f}};
    const int ntiles = REDUCE ? (N >> 7) : 1;

    for (int nt = 0; nt < ntiles; nt++) {
        const int cb = REDUCE ? (nt << 7) : ((int)blockIdx.y << 7);

        float c[2][8][4] = {};

        auto stage = [&](int buf, int kt) {
            const int koff = kt << 5;
#pragma unroll
            for (int cc = 0; cc < 2; cc++) {
                size_t asrc = (size_t)(rb + am[cc]) * DDIM + koff + ak[cc];
                uint32_t adst = (uint32_t)(((buf * 128 + am[cc]) * 40 + ak[cc]) * 2);
                cp16(uAh + adst, Ah + asrc);
                cp16(uAl + adst, Al + asrc);
                size_t bsrc = (size_t)(koff + bk[cc]) * N + cb + bn[cc];
                uint32_t bdst = (uint32_t)(((buf * 32 + bk[cc]) * 136 + bn[cc]) * 2);
                cp16(uBh + bdst, Bh + bsrc);
                if (NPASS == 3) cp16(uBl + bdst, Bl + bsrc);
            }
        };

        stage(0, 0);
        cp_commit();

        for (int kt = 0; kt < DDIM / 32; kt++) {
            if (kt < DDIM / 32 - 1) stage((kt + 1) & 1, kt + 1);
            cp_commit();
            cp_wait1();
            __syncthreads();

            const int buf = kt & 1;
            const uint32_t abufoff = (uint32_t)(buf * 128 * 40 * 2);
            const uint32_t bbufoff = (uint32_t)(buf * 32 * 136 * 2);
            const uint32_t Ahb = uAh + abufoff + a_frag_off;
            const uint32_t Alb = uAl + abufoff + a_frag_off;
            const uint32_t Bhb = uBh + bbufoff + b_frag_off;
            const uint32_t Blb = uBl + bbufoff + b_frag_off;

#pragma unroll
            for (int kk = 0; kk < 32; kk += 16) {
                // --- load Ah + Bh fragments once ---
                unsigned ah[2][4], al[2][4], bh[8][2];
#pragma unroll
                for (int mi = 0; mi < 2; mi++)
                    ldsm_x4(ah[mi][0], ah[mi][1], ah[mi][2], ah[mi][3],
                            Ahb + (uint32_t)((mi * 16 * 40 + kk) * 2));
#pragma unroll
                for (int g = 0; g < 4; g++)
                    ldsm_x4_t(bh[2*g][0], bh[2*g][1], bh[2*g+1][0], bh[2*g+1][1],
                              Bhb + (uint32_t)((kk * 136 + g * 16) * 2));

                // pass0: Ah * Bh
#pragma unroll
                for (int mi = 0; mi < 2; mi++)
#pragma unroll
                    for (int ni = 0; ni < 8; ni++)
                        mma16816(c[mi][ni], ah[mi], bh[ni]);

                // pass1 (NPASS==3 only): Ah * Bl  (stream Bl vs live Ah)
                if (NPASS == 3) {
#pragma unroll
                    for (int g = 0; g < 4; g++) {
                        unsigned t[4];
                        ldsm_x4_t(t[0], t[1], t[2], t[3],
                                  Blb + (uint32_t)((kk * 136 + g * 16) * 2));
                        unsigned b0[2] = {t[0], t[1]}, b1[2] = {t[2], t[3]};
#pragma unroll
                        for (int mi = 0; mi < 2; mi++) {
                            mma16816(c[mi][2*g],   ah[mi], b0);
                            mma16816(c[mi][2*g+1], ah[mi], b1);
                        }
                    }
                }

                // pass2: Al * Bh  (Bh still live)
#pragma unroll
                for (int mi = 0; mi < 2; mi++)
                    ldsm_x4(al[mi][0], al[mi][1], al[mi][2], al[mi][3],
                            Alb + (uint32_t)((mi * 16 * 40 + kk) * 2));
#pragma unroll
                for (int mi = 0; mi < 2; mi++)
#pragma unroll
                    for (int ni = 0; ni < 8; ni++)
                        mma16816(c[mi][ni], al[mi], bh[ni]);
            }
            __syncthreads();
        }

        if (REDUCE) {
            // fused epilogue: relu(acc + Eb) . wvec
#pragma unroll
            for (int mi = 0; mi < 2; mi++) {
                int row0 = rb + warp_m * 32 + mi * 16 + lq;
                int row1 = row0 + 8;
                const float* Eb0 = EbOrBias + (size_t)(row0 >> RPB_SHIFT) * N;
                const float* Eb1 = EbOrBias + (size_t)(row1 >> RPB_SHIFT) * N;
#pragma unroll
                for (int ni = 0; ni < 8; ni++) {
                    int col = cb + warp_n * 64 + ni * 8 + lr * 2;
                    float2 e0 = *(const float2*)&Eb0[col];
                    float2 e1 = *(const float2*)&Eb1[col];
                    float2 wv = *(const float2*)&wvec[col];
                    rs[mi][0] += fmaxf(c[mi][ni][0] + e0.x, 0.f) * wv.x
                               + fmaxf(c[mi][ni][1] + e0.y, 0.f) * wv.y;
                    rs[mi][1] += fmaxf(c[mi][ni][2] + e1.x, 0.f) * wv.x
                               + fmaxf(c[mi][ni][3] + e1.y, 0.f) * wv.y;
                }
            }
        } else {
            // plain store epilogue: C = acc + bias
#pragma unroll
            for (int mi = 0; mi < 2; mi++) {
                int row0 = rb + warp_m * 32 + mi * 16 + lq;
                int row1 = row0 + 8;
#pragma unroll
                for (int ni = 0; ni < 8; ni++) {
                    int col = cb + warp_n * 64 + ni * 8 + lr * 2;
                    float2 bv = *(const float2*)&EbOrBias[col];
                    float2 o0, o1;
                    o0.x = c[mi][ni][0] + bv.x; o0.y = c[mi][ni][1] + bv.y;
                    o1.x = c[mi][ni][2] + bv.x; o1.y = c[mi][ni][3] + bv.y;
                    *(float2*)&out[(size_t)row0 * N + col] = o0;
                    *(float2*)&out[(size_t)row1 * N + col] = o1;
                }
            }
        }
    }

    if (REDUCE) {
        // reduce across the 4 lanes sharing each row
#pragma unroll
        for (int mi = 0; mi < 2; mi++)
#pragma unroll
            for (int h = 0; h < 2; h++) {
                float s = rs[mi][h];
                s += __shfl_xor_sync(0xffffffffu, s, 1);
                s += __shfl_xor_sync(0xffffffffu, s, 2);
                if (lr == 0) red[(warp_m * 32 + mi * 16 + h * 8 + lq) * 2 + warp_n] = s;
            }
        __syncthreads();
        if (tid < 128) {
            float addv = addsc ? *addsc : 0.f;
            out[rb + tid] = red[tid * 2 + 0] + red[tid * 2 + 1] + addv;
        }
    }
}

// ---------------------------------------------------------------------------
// K4: per-b softmax over T=32 then x_hat = sum_t alpha_t * X[b,t,:], split out
// ---------------------------------------------------------------------------
__global__ void softmax_xhat_split_kernel(const float* __restrict__ e,
                                          const float* __restrict__ X,
                                          __half* __restrict__ xh,
                                          __half* __restrict__ xl)
{
    int b = blockIdx.x;
    __shared__ float alpha[TDIM];
    int tid = threadIdx.x;   // 128 threads
    if (tid < 32) {
        float v = e[b * TDIM + tid];
        float m = v;
#pragma unroll
        for (int off = 16; off >= 1; off >>= 1)
            m = fmaxf(m, __shfl_xor_sync(0xffffffffu, m, off));
        float ex = __expf(v - m);
        float s = ex;
#pragma unroll
        for (int off = 16; off >= 1; off >>= 1)
            s += __shfl_xor_sync(0xffffffffu, s, off);
        alpha[tid] = ex / s;
    }
    __syncthreads();
    const float* Xb = X + (size_t)b * TDIM * DDIM;
#pragma unroll 1
    for (int d = tid; d < DDIM; d += 128) {
        float s = 0.f;
#pragma unroll
        for (int t = 0; t < TDIM; t++) s += alpha[t] * Xb[t * DDIM + d];
        __half hh = __float2half_rn(s);
        xh[(size_t)b * DDIM + d] = hh;
        xl[(size_t)b * DDIM + d] = __float2half_rn(s - __half2float(hh));
    }
}

// ---------------------------------------------------------------------------
extern "C" void kernel_launch(void* const* d_in, const int* in_sizes, int n_in,
                              void* d_out, int out_size)
{
    const float* X  = (const float*)d_in[0];
    const float* G  = (const float*)d_in[1];
    const float* W1 = (const float*)d_in[2];
    const float* b1 = (const float*)d_in[3];
    const float* w2 = (const float*)d_in[4];
    // d_in[5] = b2: softmax shift-invariant, unused
    const float* M1 = (const float*)d_in[6];
    const float* c1 = (const float*)d_in[7];
    const float* m2 = (const float*)d_in[8];
    const float* c2 = (const float*)d_in[9];
    float* out = (float*)d_out;

    float *E1, *E2, *ebuf;
    cudaGetSymbolAddress((void**)&E1,   E1_buf);
    cudaGetSymbolAddress((void**)&E2,   E2_buf);
    cudaGetSymbolAddress((void**)&ebuf, e_buf);

    __half *Xh, *Xl, *Gh, *Gl, *W1h, *W1l, *M1h, *M1l, *ghh, *ghl, *xhh, *xhl;
    cudaGetSymbolAddress((void**)&Xh,  Xh_buf);
    cudaGetSymbolAddress((void**)&Xl,  Xl_buf);
    cudaGetSymbolAddress((void**)&Gh,  Gh_buf);
    cudaGetSymbolAddress((void**)&Gl,  Gl_buf);
    cudaGetSymbolAddress((void**)&W1h, W1h_buf);
    cudaGetSymbolAddress((void**)&W1l, W1l_buf);
    cudaGetSymbolAddress((void**)&M1h, M1h_buf);
    cudaGetSymbolAddress((void**)&M1l, M1l_buf);
    cudaGetSymbolAddress((void**)&ghh, ghh_buf);
    cudaGetSymbolAddress((void**)&ghl, ghl_buf);
    cudaGetSymbolAddress((void**)&xhh, xhh_buf);
    cudaGetSymbolAddress((void**)&xhl, xhl_buf);

    cudaFuncSetAttribute((const void*)mma_gemm<5, true, 2>,
                         cudaFuncAttributeMaxDynamicSharedMemorySize, SMEM_BYTES);
    cudaFuncSetAttribute((const void*)mma_gemm<4, true, 2>,
                         cudaFuncAttributeMaxDynamicSharedMemorySize, SMEM_BYTES);
    cudaFuncSetAttribute((const void*)mma_gemm<0, false, 3>,
                         cudaFuncAttributeMaxDynamicSharedMemorySize, SMEM_BYTES);

    // Launch order puts K3 (dominant GEMM) at index 5 for ncu -s 5 -c 1.
    // [0] split X
    split_fp16_kernel<<<(BDIM * TDIM * DDIM / 4) / 256, 256>>>(X, Xh, Xl);
    // [1] split W1
    split_fp16_kernel<<<(2 * DDIM * HDIM / 4) / 256, 256>>>(W1, W1h, W1l);
    // [2] g_hat (split output)
    gmean_split_kernel<<<(BDIM * DDIM) / 256, 256>>>(G, ghh, ghl);
    // [3] K2: E1 = g_hat @ W1[:512] + b1   (4096 x 1024, 3-pass)
    mma_gemm<0, false, 3><<<dim3(BDIM / 128, HDIM / 128), 256, SMEM_BYTES>>>(
        ghh, ghl, W1h, W1l, b1, nullptr, nullptr, E1, HDIM);
    // [4] split G
    split_fp16_kernel<<<(BDIM * KDIM * DDIM / 4) / 256, 256>>>(G, Gh, Gl);
    // [5] K3: e[b,t] = sum_h relu( X@W1[512:] + E1 ) * w2   (M = 131072, 2-pass)
    mma_gemm<5, true, 2><<<(BDIM * TDIM) / 128, 256, SMEM_BYTES>>>(
        Xh, Xl, W1h + (size_t)DDIM * HDIM, W1l + (size_t)DDIM * HDIM,
        E1, w2, nullptr, ebuf, HDIM);
    // [6] softmax over T + x_hat (split output)
    softmax_xhat_split_kernel<<<BDIM, 128>>>(ebuf, X, xhh, xhl);
    // [7] split M1
    split_fp16_kernel<<<(2 * DDIM * H2DIM / 4) / 256, 256>>>(M1, M1h, M1l);
    // [8] K5: E2 = x_hat @ M1[:512] + c1   (4096 x 2048, 3-pass)
    mma_gemm<0, false, 3><<<dim3(BDIM / 128, H2DIM / 128), 256, SMEM_BYTES>>>(
        xhh, xhl, M1h, M1l, c1, nullptr, nullptr, E2, H2DIM);
    // [9] K6: logits = ... (M = 65536, 2-pass)
    mma_gemm<4, true, 2><<<(BDIM * KDIM) / 128, 256, SMEM_BYTES>>>(
        Gh, Gl, M1h + (size_t)DDIM * H2DIM, M1l + (size_t)DDIM * H2DIM,
        E2, m2, c2, out, H2DIM);
}

// round 9
// speedup vs baseline: 7.2880x; 1.7629x over previous
#include <cuda_runtime.h>
#include <cuda_fp16.h>
#include <cstdint>

// Problem constants
#define BDIM  4096
#define TDIM  32
#define KDIM  16
#define DDIM  512
#define HDIM  1024   // = 2*D
#define H2DIM 2048   // = 2*H

// NOTE: harness PTX target is compute_103 (no 'a') -> tcgen05/TMEM rejected.
// Legacy mma.sync HMMA is the tensor path.
// Precision plan: big GEMMs single-pass fp16 (A,B both ~2^-11 quant, combined
// rel_err ~2.5e-4 on logits); small GEMMs (E1/E2) 2-pass (A split hi+lo).

// ---------------------------------------------------------------------------
// Scratch (device globals: allocation-free rule)
// ---------------------------------------------------------------------------
__device__ float E1_buf[BDIM * HDIM];
__device__ float E2_buf[BDIM * H2DIM];
__device__ float e_buf[BDIM * TDIM];

__device__ __half Xh_buf[BDIM * TDIM * DDIM];
__device__ __half Gh_buf[BDIM * KDIM * DDIM];
__device__ __half W1h_buf[2 * DDIM * HDIM];   // full W1 (1024 x 1024)
__device__ __half M1h_buf[2 * DDIM * H2DIM];  // full M1 (1024 x 2048)
__device__ __half ghh_buf[BDIM * DDIM];
__device__ __half ghl_buf[BDIM * DDIM];
__device__ __half xhh_buf[BDIM * DDIM];
__device__ __half xhl_buf[BDIM * DDIM];

// ---------------------------------------------------------------------------
// PTX helpers
// ---------------------------------------------------------------------------
__device__ __forceinline__ void cp16(uint32_t dst, const void* src) {
    asm volatile("cp.async.cg.shared.global [%0], [%1], 16;\n"
                 :: "r"(dst), "l"(src) : "memory");
}
__device__ __forceinline__ void cp_commit() {
    asm volatile("cp.async.commit_group;\n" ::: "memory");
}
__device__ __forceinline__ void cp_wait1() {
    asm volatile("cp.async.wait_group 1;\n" ::: "memory");
}
__device__ __forceinline__ void ldsm_x4(unsigned& d0, unsigned& d1, unsigned& d2,
                                        unsigned& d3, uint32_t addr) {
    asm volatile("ldmatrix.sync.aligned.m8n8.x4.shared.b16 {%0,%1,%2,%3}, [%4];\n"
                 : "=r"(d0), "=r"(d1), "=r"(d2), "=r"(d3) : "r"(addr));
}
__device__ __forceinline__ void ldsm_x4_t(unsigned& d0, unsigned& d1, unsigned& d2,
                                          unsigned& d3, uint32_t addr) {
    asm volatile("ldmatrix.sync.aligned.m8n8.x4.trans.shared.b16 {%0,%1,%2,%3}, [%4];\n"
                 : "=r"(d0), "=r"(d1), "=r"(d2), "=r"(d3) : "r"(addr));
}
__device__ __forceinline__ void mma16816(float c[4], const unsigned a[4], const unsigned b[2]) {
    asm volatile(
        "mma.sync.aligned.m16n8k16.row.col.f32.f16.f16.f32 "
        "{%0,%1,%2,%3}, {%4,%5,%6,%7}, {%8,%9}, {%0,%1,%2,%3};\n"
        : "+f"(c[0]), "+f"(c[1]), "+f"(c[2]), "+f"(c[3])
        : "r"(a[0]), "r"(a[1]), "r"(a[2]), "r"(a[3]), "r"(b[0]), "r"(b[1]));
}

// ---------------------------------------------------------------------------
// convert-only: hi = fp16(x)
// ---------------------------------------------------------------------------
__global__ void conv_fp16_kernel(const float* __restrict__ src,
                                 __half* __restrict__ hi)
{
    int i = blockIdx.x * blockDim.x + threadIdx.x;
    float4 v = ((const float4*)src)[i];
    __half h[4];
    h[0] = __float2half_rn(v.x); h[1] = __float2half_rn(v.y);
    h[2] = __float2half_rn(v.z); h[3] = __float2half_rn(v.w);
    ((uint2*)hi)[i] = *(uint2*)h;
}

// ---------------------------------------------------------------------------
// K1: g_hat = mean_k G, split-fp16 output (hi + lo, feeds 2-pass K2)
// ---------------------------------------------------------------------------
__global__ void gmean_split_kernel(const float* __restrict__ G,
                                   __half* __restrict__ h,
                                   __half* __restrict__ l)
{
    int idx = blockIdx.x * blockDim.x + threadIdx.x;   // over B*D
    int b = idx >> 9;
    int d = idx & 511;
    const float* g = G + (size_t)b * KDIM * DDIM + d;
    float s = 0.f;
#pragma unroll
    for (int k = 0; k < KDIM; k++) s += g[k * DDIM];
    s *= (1.0f / KDIM);
    __half hh = __float2half_rn(s);
    h[idx] = hh;
    l[idx] = __float2half_rn(s - __half2float(hh));
}

// ---------------------------------------------------------------------------
// Tensor-core fp16 GEMM, BM=128, BN=128, BK=32, 8 warps (4m x 2n).
// NPASS=1: AhBh.  NPASS=2: AhBh + AlBh.  NPASS=3: + AhBl.
// REDUCE=true : out[row] = sum_n relu(acc + Eb[row>>RPB_SHIFT, n]) * wvec[n] (+sc)
//               grid = (M/128), loops all N tiles internally.
// REDUCE=false: out[row,col] = acc + bias[col]; grid = (M/128, N/128).
// ---------------------------------------------------------------------------
constexpr int SMEM_BYTES = 2*128*40*2 * 2   // sAh + sAl
                         + 2*32*136*2 * 2   // sBh + sBl
                         + 128*2*4;         // red

template <int RPB_SHIFT, bool REDUCE, int NPASS>
__global__ void __launch_bounds__(256, 2) mma_gemm(
    const __half* __restrict__ Ah, const __half* __restrict__ Al,
    const __half* __restrict__ Bh, const __half* __restrict__ Bl,
    const float* __restrict__ EbOrBias,
    const float* __restrict__ wvec,
    const float* __restrict__ addsc,
    float* __restrict__ out,
    int N)
{
    extern __shared__ __align__(16) char smraw[];
    __half* sAh = (__half*)smraw;                // [2][128][40]
    __half* sAl = sAh + 2 * 128 * 40;
    __half* sBh = sAl + 2 * 128 * 40;            // [2][32][136]
    __half* sBl = sBh + 2 * 32 * 136;
    float* red = (float*)(sBl + 2 * 32 * 136);   // [128][2]

    const int tid  = threadIdx.x;
    const int lane = tid & 31;
    const int wid  = tid >> 5;
    const int warp_m = wid & 3;
    const int warp_n = wid >> 2;
    const int lq = lane >> 2, lr = lane & 3;
    const int rb = blockIdx.x * 128;

    const uint32_t uAh = (uint32_t)__cvta_generic_to_shared(sAh);
    const uint32_t uAl = (uint32_t)__cvta_generic_to_shared(sAl);
    const uint32_t uBh = (uint32_t)__cvta_generic_to_shared(sBh);
    const uint32_t uBl = (uint32_t)__cvta_generic_to_shared(sBl);

    // staging chunk coords (2 x 16B chunks per thread per tile)
    int am[2], ak[2], bk[2], bn[2];
#pragma unroll
    for (int c = 0; c < 2; c++) {
        int cid = tid + c * 256;
        am[c] = cid >> 2;  ak[c] = (cid & 3) << 3;
        bk[c] = cid >> 4;  bn[c] = (cid & 15) << 3;
    }

    // ldmatrix per-lane address components
    const uint32_t a_frag_off =
        (uint32_t)(((warp_m * 32 + (lane & 15)) * 40 + ((lane & 16) >> 1)) * 2);
    const uint32_t b_frag_off =
        (uint32_t)(((lane & 15) * 136 + warp_n * 64 + ((lane & 16) >> 1)) * 2);

    float rs[2][2] = {{0.f, 0.f}, {0.f, 0.f}};
    const int ntiles = REDUCE ? (N >> 7) : 1;

    for (int nt = 0; nt < ntiles; nt++) {
        const int cb = REDUCE ? (nt << 7) : ((int)blockIdx.y << 7);

        float c[2][8][4] = {};

        auto stage = [&](int buf, int kt) {
            const int koff = kt << 5;
#pragma unroll
            for (int cc = 0; cc < 2; cc++) {
                size_t asrc = (size_t)(rb + am[cc]) * DDIM + koff + ak[cc];
                uint32_t adst = (uint32_t)(((buf * 128 + am[cc]) * 40 + ak[cc]) * 2);
                cp16(uAh + adst, Ah + asrc);
                if (NPASS >= 2) cp16(uAl + adst, Al + asrc);
                size_t bsrc = (size_t)(koff + bk[cc]) * N + cb + bn[cc];
                uint32_t bdst = (uint32_t)(((buf * 32 + bk[cc]) * 136 + bn[cc]) * 2);
                cp16(uBh + bdst, Bh + bsrc);
                if (NPASS == 3) cp16(uBl + bdst, Bl + bsrc);
            }
        };

        stage(0, 0);
        cp_commit();

        for (int kt = 0; kt < DDIM / 32; kt++) {
            if (kt < DDIM / 32 - 1) stage((kt + 1) & 1, kt + 1);
            cp_commit();
            cp_wait1();
            __syncthreads();

            const int buf = kt & 1;
            const uint32_t abufoff = (uint32_t)(buf * 128 * 40 * 2);
            const uint32_t bbufoff = (uint32_t)(buf * 32 * 136 * 2);
            const uint32_t Ahb = uAh + abufoff + a_frag_off;
            const uint32_t Alb = uAl + abufoff + a_frag_off;
            const uint32_t Bhb = uBh + bbufoff + b_frag_off;
            const uint32_t Blb = uBl + bbufoff + b_frag_off;

#pragma unroll
            for (int kk = 0; kk < 32; kk += 16) {
                // --- load Ah + Bh fragments once ---
                unsigned ah[2][4], bh[8][2];
#pragma unroll
                for (int mi = 0; mi < 2; mi++)
                    ldsm_x4(ah[mi][0], ah[mi][1], ah[mi][2], ah[mi][3],
                            Ahb + (uint32_t)((mi * 16 * 40 + kk) * 2));
#pragma unroll
                for (int g = 0; g < 4; g++)
                    ldsm_x4_t(bh[2*g][0], bh[2*g][1], bh[2*g+1][0], bh[2*g+1][1],
                              Bhb + (uint32_t)((kk * 136 + g * 16) * 2));

                // pass0: Ah * Bh
#pragma unroll
                for (int mi = 0; mi < 2; mi++)
#pragma unroll
                    for (int ni = 0; ni < 8; ni++)
                        mma16816(c[mi][ni], ah[mi], bh[ni]);

                // pass1 (NPASS==3 only): Ah * Bl  (stream Bl vs live Ah)
                if (NPASS == 3) {
#pragma unroll
                    for (int g = 0; g < 4; g++) {
                        unsigned t[4];
                        ldsm_x4_t(t[0], t[1], t[2], t[3],
                                  Blb + (uint32_t)((kk * 136 + g * 16) * 2));
                        unsigned b0[2] = {t[0], t[1]}, b1[2] = {t[2], t[3]};
#pragma unroll
                        for (int mi = 0; mi < 2; mi++) {
                            mma16816(c[mi][2*g],   ah[mi], b0);
                            mma16816(c[mi][2*g+1], ah[mi], b1);
                        }
                    }
                }

                // pass2 (NPASS>=2): Al * Bh  (Bh still live)
                if (NPASS >= 2) {
                    unsigned al[2][4];
#pragma unroll
                    for (int mi = 0; mi < 2; mi++)
                        ldsm_x4(al[mi][0], al[mi][1], al[mi][2], al[mi][3],
                                Alb + (uint32_t)((mi * 16 * 40 + kk) * 2));
#pragma unroll
                    for (int mi = 0; mi < 2; mi++)
#pragma unroll
                        for (int ni = 0; ni < 8; ni++)
                            mma16816(c[mi][ni], al[mi], bh[ni]);
                }
            }
            __syncthreads();
        }

        if (REDUCE) {
            // fused epilogue: relu(acc + Eb) . wvec
#pragma unroll
            for (int mi = 0; mi < 2; mi++) {
                int row0 = rb + warp_m * 32 + mi * 16 + lq;
                int row1 = row0 + 8;
                const float* Eb0 = EbOrBias + (size_t)(row0 >> RPB_SHIFT) * N;
                const float* Eb1 = EbOrBias + (size_t)(row1 >> RPB_SHIFT) * N;
#pragma unroll
                for (int ni = 0; ni < 8; ni++) {
                    int col = cb + warp_n * 64 + ni * 8 + lr * 2;
                    float2 e0 = *(const float2*)&Eb0[col];
                    float2 e1 = *(const float2*)&Eb1[col];
                    float2 wv = *(const float2*)&wvec[col];
                    rs[mi][0] += fmaxf(c[mi][ni][0] + e0.x, 0.f) * wv.x
                               + fmaxf(c[mi][ni][1] + e0.y, 0.f) * wv.y;
                    rs[mi][1] += fmaxf(c[mi][ni][2] + e1.x, 0.f) * wv.x
                               + fmaxf(c[mi][ni][3] + e1.y, 0.f) * wv.y;
                }
            }
        } else {
            // plain store epilogue: C = acc + bias
#pragma unroll
            for (int mi = 0; mi < 2; mi++) {
                int row0 = rb + warp_m * 32 + mi * 16 + lq;
                int row1 = row0 + 8;
#pragma unroll
                for (int ni = 0; ni < 8; ni++) {
                    int col = cb + warp_n * 64 + ni * 8 + lr * 2;
                    float2 bv = *(const float2*)&EbOrBias[col];
                    float2 o0, o1;
                    o0.x = c[mi][ni][0] + bv.x; o0.y = c[mi][ni][1] + bv.y;
                    o1.x = c[mi][ni][2] + bv.x; o1.y = c[mi][ni][3] + bv.y;
                    *(float2*)&out[(size_t)row0 * N + col] = o0;
                    *(float2*)&out[(size_t)row1 * N + col] = o1;
                }
            }
        }
    }

    if (REDUCE) {
        // reduce across the 4 lanes sharing each row
#pragma unroll
        for (int mi = 0; mi < 2; mi++)
#pragma unroll
            for (int h = 0; h < 2; h++) {
                float s = rs[mi][h];
                s += __shfl_xor_sync(0xffffffffu, s, 1);
                s += __shfl_xor_sync(0xffffffffu, s, 2);
                if (lr == 0) red[(warp_m * 32 + mi * 16 + h * 8 + lq) * 2 + warp_n] = s;
            }
        __syncthreads();
        if (tid < 128) {
            float addv = addsc ? *addsc : 0.f;
            out[rb + tid] = red[tid * 2 + 0] + red[tid * 2 + 1] + addv;
        }
    }
}

// ---------------------------------------------------------------------------
// K4: per-b softmax over T=32 then x_hat = sum_t alpha_t * Xh[b,t,:], split out.
// Reads fp16 X (error 2^-12, inside the GEMM quantization budget).
// 128 threads; each owns 4 consecutive d (one uint2 per t).
// ---------------------------------------------------------------------------
__global__ void softmax_xhat_split_kernel(const float* __restrict__ e,
                                          const __half* __restrict__ Xh,
                                          __half* __restrict__ xh,
                                          __half* __restrict__ xl)
{
    int b = blockIdx.x;
    __shared__ float alpha[TDIM];
    int tid = threadIdx.x;   // 128 threads
    if (tid < 32) {
        float v = e[b * TDIM + tid];
        float m = v;
#pragma unroll
        for (int off = 16; off >= 1; off >>= 1)
            m = fmaxf(m, __shfl_xor_sync(0xffffffffu, m, off));
        float ex = __expf(v - m);
        float s = ex;
#pragma unroll
        for (int off = 16; off >= 1; off >>= 1)
            s += __shfl_xor_sync(0xffffffffu, s, off);
        alpha[tid] = ex / s;
    }
    __syncthreads();
    const __half* Xb = Xh + (size_t)b * TDIM * DDIM + tid * 4;
    float s0 = 0.f, s1 = 0.f, s2 = 0.f, s3 = 0.f;
#pragma unroll
    for (int t = 0; t < TDIM; t++) {
        uint2 raw = *(const uint2*)&Xb[t * DDIM];
        __half2 p0 = *(__half2*)&raw.x;
        __half2 p1 = *(__half2*)&raw.y;
        float a = alpha[t];
        s0 += a * __low2float(p0);  s1 += a * __high2float(p0);
        s2 += a * __low2float(p1);  s3 += a * __high2float(p1);
    }
    __half hh[4], ll[4];
    hh[0] = __float2half_rn(s0); ll[0] = __float2half_rn(s0 - __half2float(hh[0]));
    hh[1] = __float2half_rn(s1); ll[1] = __float2half_rn(s1 - __half2float(hh[1]));
    hh[2] = __float2half_rn(s2); ll[2] = __float2half_rn(s2 - __half2float(hh[2]));
    hh[3] = __float2half_rn(s3); ll[3] = __float2half_rn(s3 - __half2float(hh[3]));
    size_t o = ((size_t)b * DDIM + tid * 4) >> 2;
    ((uint2*)xh)[o] = *(uint2*)hh;
    ((uint2*)xl)[o] = *(uint2*)ll;
}

// ---------------------------------------------------------------------------
extern "C" void kernel_launch(void* const* d_in, const int* in_sizes, int n_in,
                              void* d_out, int out_size)
{
    const float* X  = (const float*)d_in[0];
    const float* G  = (const float*)d_in[1];
    const float* W1 = (const float*)d_in[2];
    const float* b1 = (const float*)d_in[3];
    const float* w2 = (const float*)d_in[4];
    // d_in[5] = b2: softmax shift-invariant, unused
    const float* M1 = (const float*)d_in[6];
    const float* c1 = (const float*)d_in[7];
    const float* m2 = (const float*)d_in[8];
    const float* c2 = (const float*)d_in[9];
    float* out = (float*)d_out;

    float *E1, *E2, *ebuf;
    cudaGetSymbolAddress((void**)&E1,   E1_buf);
    cudaGetSymbolAddress((void**)&E2,   E2_buf);
    cudaGetSymbolAddress((void**)&ebuf, e_buf);

    __half *Xh, *Gh, *W1h, *M1h, *ghh, *ghl, *xhh, *xhl;
    cudaGetSymbolAddress((void**)&Xh,  Xh_buf);
    cudaGetSymbolAddress((void**)&Gh,  Gh_buf);
    cudaGetSymbolAddress((void**)&W1h, W1h_buf);
    cudaGetSymbolAddress((void**)&M1h, M1h_buf);
    cudaGetSymbolAddress((void**)&ghh, ghh_buf);
    cudaGetSymbolAddress((void**)&ghl, ghl_buf);
    cudaGetSymbolAddress((void**)&xhh, xhh_buf);
    cudaGetSymbolAddress((void**)&xhl, xhl_buf);

    cudaFuncSetAttribute((const void*)mma_gemm<5, true, 1>,
                         cudaFuncAttributeMaxDynamicSharedMemorySize, SMEM_BYTES);
    cudaFuncSetAttribute((const void*)mma_gemm<4, true, 1>,
                         cudaFuncAttributeMaxDynamicSharedMemorySize, SMEM_BYTES);
    cudaFuncSetAttribute((const void*)mma_gemm<0, false, 2>,
                         cudaFuncAttributeMaxDynamicSharedMemorySize, SMEM_BYTES);

    // [0] convert X -> fp16
    conv_fp16_kernel<<<(BDIM * TDIM * DDIM / 4) / 256, 256>>>(X, Xh);
    // [1] convert W1 -> fp16
    conv_fp16_kernel<<<(2 * DDIM * HDIM / 4) / 256, 256>>>(W1, W1h);
    // [2] g_hat (split hi/lo, feeds 2-pass K2)
    gmean_split_kernel<<<(BDIM * DDIM) / 256, 256>>>(G, ghh, ghl);
    // [3] K2: E1 = g_hat @ W1[:512] + b1   (4096 x 1024, 2-pass)
    mma_gemm<0, false, 2><<<dim3(BDIM / 128, HDIM / 128), 256, SMEM_BYTES>>>(
        ghh, ghl, W1h, nullptr, b1, nullptr, nullptr, E1, HDIM);
    // [4] convert G -> fp16
    conv_fp16_kernel<<<(BDIM * KDIM * DDIM / 4) / 256, 256>>>(G, Gh);
    // [5] K3: e[b,t] = sum_h relu( X@W1[512:] + E1 ) * w2   (M = 131072, 1-pass)
    mma_gemm<5, true, 1><<<(BDIM * TDIM) / 128, 256, SMEM_BYTES>>>(
        Xh, nullptr, W1h + (size_t)DDIM * HDIM, nullptr,
        E1, w2, nullptr, ebuf, HDIM);
    // [6] softmax over T + x_hat (split output)
    softmax_xhat_split_kernel<<<BDIM, 128>>>(ebuf, Xh, xhh, xhl);
    // [7] convert M1 -> fp16
    conv_fp16_kernel<<<(2 * DDIM * H2DIM / 4) / 256, 256>>>(M1, M1h);
    // [8] K5: E2 = x_hat @ M1[:512] + c1   (4096 x 2048, 2-pass)
    mma_gemm<0, false, 2><<<dim3(BDIM / 128, H2DIM / 128), 256, SMEM_BYTES>>>(
        xhh, xhl, M1h, nullptr, c1, nullptr, nullptr, E2, H2DIM);
    // [9] K6: logits = sum_j relu( G@M1[512:] + E2 ) * m2 + c2  (M = 65536, 1-pass)
    mma_gemm<4, true, 1><<<(BDIM * KDIM) / 128, 256, SMEM_BYTES>>>(
        Gh, nullptr, M1h + (size_t)DDIM * H2DIM, nullptr,
        E2, m2, c2, out, H2DIM);
}

// round 10
// speedup vs baseline: 8.9407x; 1.2268x over previous
#include <cuda_runtime.h>
#include <cuda_fp16.h>
#include <cstdint>

// Problem constants
#define BDIM  4096
#define TDIM  32
#define KDIM  16
#define DDIM  512
#define HDIM  1024   // = 2*D
#define H2DIM 2048   // = 2*H

// NOTE: harness PTX target is compute_103 (no 'a') -> tcgen05/TMEM rejected.
// Legacy mma.sync HMMA is the tensor path. All GEMMs single-pass fp16
// (every operand ~2^-11 quant; combined logits rel_err ~3e-4, gate 1e-3).

// ---------------------------------------------------------------------------
// Scratch (device globals: allocation-free rule)
// ---------------------------------------------------------------------------
__device__ float E1_buf[BDIM * HDIM];
__device__ float E2_buf[BDIM * H2DIM];
__device__ float e_buf[BDIM * TDIM];

__device__ __half Xh_buf[BDIM * TDIM * DDIM];
__device__ __half Gh_buf[BDIM * KDIM * DDIM];
__device__ __half W1h_buf[2 * DDIM * HDIM];   // full W1 (1024 x 1024)
__device__ __half M1h_buf[2 * DDIM * H2DIM];  // full M1 (1024 x 2048)
__device__ __half ghh_buf[BDIM * DDIM];
__device__ __half xhh_buf[BDIM * DDIM];

// ---------------------------------------------------------------------------
// PTX helpers
// ---------------------------------------------------------------------------
__device__ __forceinline__ void cp16(uint32_t dst, const void* src) {
    asm volatile("cp.async.cg.shared.global [%0], [%1], 16;\n"
                 :: "r"(dst), "l"(src) : "memory");
}
__device__ __forceinline__ void cp_commit() {
    asm volatile("cp.async.commit_group;\n" ::: "memory");
}
__device__ __forceinline__ void cp_wait1() {
    asm volatile("cp.async.wait_group 1;\n" ::: "memory");
}
__device__ __forceinline__ void ldsm_x4(unsigned& d0, unsigned& d1, unsigned& d2,
                                        unsigned& d3, uint32_t addr) {
    asm volatile("ldmatrix.sync.aligned.m8n8.x4.shared.b16 {%0,%1,%2,%3}, [%4];\n"
                 : "=r"(d0), "=r"(d1), "=r"(d2), "=r"(d3) : "r"(addr));
}
__device__ __forceinline__ void ldsm_x4_t(unsigned& d0, unsigned& d1, unsigned& d2,
                                          unsigned& d3, uint32_t addr) {
    asm volatile("ldmatrix.sync.aligned.m8n8.x4.trans.shared.b16 {%0,%1,%2,%3}, [%4];\n"
                 : "=r"(d0), "=r"(d1), "=r"(d2), "=r"(d3) : "r"(addr));
}
__device__ __forceinline__ void mma16816(float c[4], const unsigned a[4], const unsigned b[2]) {
    asm volatile(
        "mma.sync.aligned.m16n8k16.row.col.f32.f16.f16.f32 "
        "{%0,%1,%2,%3}, {%4,%5,%6,%7}, {%8,%9}, {%0,%1,%2,%3};\n"
        : "+f"(c[0]), "+f"(c[1]), "+f"(c[2]), "+f"(c[3])
        : "r"(a[0]), "r"(a[1]), "r"(a[2]), "r"(a[3]), "r"(b[0]), "r"(b[1]));
}

// ---------------------------------------------------------------------------
// convert-only: hi = fp16(x)
// ---------------------------------------------------------------------------
__global__ void conv_fp16_kernel(const float* __restrict__ src,
                                 __half* __restrict__ hi)
{
    int i = blockIdx.x * blockDim.x + threadIdx.x;
    float4 v = ((const float4*)src)[i];
    __half h[4];
    h[0] = __float2half_rn(v.x); h[1] = __float2half_rn(v.y);
    h[2] = __float2half_rn(v.z); h[3] = __float2half_rn(v.w);
    ((uint2*)hi)[i] = *(uint2*)h;
}

// ---------------------------------------------------------------------------
// K1: g_hat = mean_k G -> fp16
// ---------------------------------------------------------------------------
__global__ void gmean_kernel(const float* __restrict__ G,
                             __half* __restrict__ h)
{
    int idx = blockIdx.x * blockDim.x + threadIdx.x;   // over B*D
    int b = idx >> 9;
    int d = idx & 511;
    const float* g = G + (size_t)b * KDIM * DDIM + d;
    float s = 0.f;
#pragma unroll
    for (int k = 0; k < KDIM; k++) s += g[k * DDIM];
    h[idx] = __float2half_rn(s * (1.0f / KDIM));
}

// ---------------------------------------------------------------------------
// fp16 tensor-core GEMM, BM=128, BN=128, BK=32, 8 warps (4m x 2n).
// 3-stage cp.async pipeline, single __syncthreads per k-tile.
// REDUCE=true : out[row] = sum_n relu(acc + Eb[row>>RPB_SHIFT, n]) * wvec[n] (+sc)
//               grid = (M/128), loops all N tiles internally.
// REDUCE=false: out[row,col] = acc + bias[col]; grid = (M/128, N/128).
// ---------------------------------------------------------------------------
constexpr int ASZ = 128 * 40 * 2;     // one A stage (bytes)
constexpr int BSZ = 32 * 136 * 2;     // one B stage (bytes)
constexpr int SMEM_BYTES = 3 * ASZ + 3 * BSZ + 128 * 2 * 4;
constexpr int NKT = DDIM / 32;        // 16? no: 512/32 = 16 k-tiles... see below
// NKT = 16 k-tiles of BK=32 over K=512.

template <int RPB_SHIFT, bool REDUCE>
__global__ void __launch_bounds__(256, 2) mma_gemm(
    const __half* __restrict__ Ah,
    const __half* __restrict__ Bh,
    const float* __restrict__ EbOrBias,
    const float* __restrict__ wvec,
    const float* __restrict__ addsc,
    float* __restrict__ out,
    int N)
{
    extern __shared__ __align__(16) char smraw[];
    // [3 A stages][3 B stages][red]
    float* red = (float*)(smraw + 3 * ASZ + 3 * BSZ);

    const int tid  = threadIdx.x;
    const int lane = tid & 31;
    const int wid  = tid >> 5;
    const int warp_m = wid & 3;
    const int warp_n = wid >> 2;
    const int lq = lane >> 2, lr = lane & 3;
    const int rb = blockIdx.x * 128;

    const uint32_t uS = (uint32_t)__cvta_generic_to_shared(smraw);
    const uint32_t uA = uS;                 // A stages base
    const uint32_t uB = uS + 3 * ASZ;       // B stages base

    // staging chunk coords (A: 2 chunks, B: 2 chunks per thread per tile)
    int am[2], ak[2], bk[2], bn[2];
#pragma unroll
    for (int c = 0; c < 2; c++) {
        int cid = tid + c * 256;
        am[c] = cid >> 2;  ak[c] = (cid & 3) << 3;
        bk[c] = cid >> 4;  bn[c] = (cid & 15) << 3;
    }

    // ldmatrix per-lane address components
    const uint32_t a_frag_off =
        (uint32_t)(((warp_m * 32 + (lane & 15)) * 40 + ((lane & 16) >> 1)) * 2);
    const uint32_t b_frag_off =
        (uint32_t)(((lane & 15) * 136 + warp_n * 64 + ((lane & 16) >> 1)) * 2);

    float rs[2][2] = {{0.f, 0.f}, {0.f, 0.f}};
    const int ntiles = REDUCE ? (N >> 7) : 1;

    for (int nt = 0; nt < ntiles; nt++) {
        const int cb = REDUCE ? (nt << 7) : ((int)blockIdx.y << 7);

        float c[2][8][4] = {};

        auto stage = [&](int buf, int kt) {
            const int koff = kt << 5;
            const uint32_t adst0 = uA + (uint32_t)(buf * ASZ);
            const uint32_t bdst0 = uB + (uint32_t)(buf * BSZ);
#pragma unroll
            for (int cc = 0; cc < 2; cc++) {
                cp16(adst0 + (uint32_t)((am[cc] * 40 + ak[cc]) * 2),
                     Ah + (size_t)(rb + am[cc]) * DDIM + koff + ak[cc]);
                cp16(bdst0 + (uint32_t)((bk[cc] * 136 + bn[cc]) * 2),
                     Bh + (size_t)(koff + bk[cc]) * N + cb + bn[cc]);
            }
        };

        // prologue: stage kt=0,1
        stage(0, 0); cp_commit();
        stage(1, 1); cp_commit();

        const int NKT2 = DDIM / 32;   // 16
        for (int kt = 0; kt < NKT2; kt++) {
            cp_wait1();               // k-tile kt data resident
            __syncthreads();          // visible to all warps; prior buf reads done
            if (kt + 2 < NKT2) stage((kt + 2) % 3, kt + 2);
            cp_commit();              // empty commit keeps group count aligned

            const int buf = kt % 3;
            const uint32_t Ahb = uA + (uint32_t)(buf * ASZ) + a_frag_off;
            const uint32_t Bhb = uB + (uint32_t)(buf * BSZ) + b_frag_off;

#pragma unroll
            for (int kk = 0; kk < 32; kk += 16) {
                unsigned ah[2][4], bh[8][2];
#pragma unroll
                for (int mi = 0; mi < 2; mi++)
                    ldsm_x4(ah[mi][0], ah[mi][1], ah[mi][2], ah[mi][3],
                            Ahb + (uint32_t)((mi * 16 * 40 + kk) * 2));
#pragma unroll
                for (int g = 0; g < 4; g++)
                    ldsm_x4_t(bh[2*g][0], bh[2*g][1], bh[2*g+1][0], bh[2*g+1][1],
                              Bhb + (uint32_t)((kk * 136 + g * 16) * 2));
#pragma unroll
                for (int mi = 0; mi < 2; mi++)
#pragma unroll
                    for (int ni = 0; ni < 8; ni++)
                        mma16816(c[mi][ni], ah[mi], bh[ni]);
            }
        }
        __syncthreads();   // protect stage buffers before next nt prologue

        if (REDUCE) {
            // fused epilogue: relu(acc + Eb) . wvec
#pragma unroll
            for (int mi = 0; mi < 2; mi++) {
                int row0 = rb + warp_m * 32 + mi * 16 + lq;
                int row1 = row0 + 8;
                const float* Eb0 = EbOrBias + (size_t)(row0 >> RPB_SHIFT) * N;
                const float* Eb1 = EbOrBias + (size_t)(row1 >> RPB_SHIFT) * N;
#pragma unroll
                for (int ni = 0; ni < 8; ni++) {
                    int col = cb + warp_n * 64 + ni * 8 + lr * 2;
                    float2 e0 = *(const float2*)&Eb0[col];
                    float2 e1 = *(const float2*)&Eb1[col];
                    float2 wv = *(const float2*)&wvec[col];
                    rs[mi][0] += fmaxf(c[mi][ni][0] + e0.x, 0.f) * wv.x
                               + fmaxf(c[mi][ni][1] + e0.y, 0.f) * wv.y;
                    rs[mi][1] += fmaxf(c[mi][ni][2] + e1.x, 0.f) * wv.x
                               + fmaxf(c[mi][ni][3] + e1.y, 0.f) * wv.y;
                }
            }
        } else {
            // plain store epilogue: C = acc + bias
#pragma unroll
            for (int mi = 0; mi < 2; mi++) {
                int row0 = rb + warp_m * 32 + mi * 16 + lq;
                int row1 = row0 + 8;
#pragma unroll
                for (int ni = 0; ni < 8; ni++) {
                    int col = cb + warp_n * 64 + ni * 8 + lr * 2;
                    float2 bv = *(const float2*)&EbOrBias[col];
                    float2 o0, o1;
                    o0.x = c[mi][ni][0] + bv.x; o0.y = c[mi][ni][1] + bv.y;
                    o1.x = c[mi][ni][2] + bv.x; o1.y = c[mi][ni][3] + bv.y;
                    *(float2*)&out[(size_t)row0 * N + col] = o0;
                    *(float2*)&out[(size_t)row1 * N + col] = o1;
                }
            }
        }
    }

    if (REDUCE) {
        // reduce across the 4 lanes sharing each row
#pragma unroll
        for (int mi = 0; mi < 2; mi++)
#pragma unroll
            for (int h = 0; h < 2; h++) {
                float s = rs[mi][h];
                s += __shfl_xor_sync(0xffffffffu, s, 1);
                s += __shfl_xor_sync(0xffffffffu, s, 2);
                if (lr == 0) red[(warp_m * 32 + mi * 16 + h * 8 + lq) * 2 + warp_n] = s;
            }
        __syncthreads();
        if (tid < 128) {
            float addv = addsc ? *addsc : 0.f;
            out[rb + tid] = red[tid * 2 + 0] + red[tid * 2 + 1] + addv;
        }
    }
}

// ---------------------------------------------------------------------------
// K4: per-b softmax over T=32 then x_hat = sum_t alpha_t * Xh[b,t,:] -> fp16
// ---------------------------------------------------------------------------
__global__ void softmax_xhat_kernel(const float* __restrict__ e,
                                    const __half* __restrict__ Xh,
                                    __half* __restrict__ xh)
{
    int b = blockIdx.x;
    __shared__ float alpha[TDIM];
    int tid = threadIdx.x;   // 128 threads
    if (tid < 32) {
        float v = e[b * TDIM + tid];
        float m = v;
#pragma unroll
        for (int off = 16; off >= 1; off >>= 1)
            m = fmaxf(m, __shfl_xor_sync(0xffffffffu, m, off));
        float ex = __expf(v - m);
        float s = ex;
#pragma unroll
        for (int off = 16; off >= 1; off >>= 1)
            s += __shfl_xor_sync(0xffffffffu, s, off);
        alpha[tid] = ex / s;
    }
    __syncthreads();
    const __half* Xb = Xh + (size_t)b * TDIM * DDIM + tid * 4;
    float s0 = 0.f, s1 = 0.f, s2 = 0.f, s3 = 0.f;
#pragma unroll
    for (int t = 0; t < TDIM; t++) {
        uint2 raw = *(const uint2*)&Xb[t * DDIM];
        __half2 p0 = *(__half2*)&raw.x;
        __half2 p1 = *(__half2*)&raw.y;
        float a = alpha[t];
        s0 += a * __low2float(p0);  s1 += a * __high2float(p0);
        s2 += a * __low2float(p1);  s3 += a * __high2float(p1);
    }
    __half hh[4];
    hh[0] = __float2half_rn(s0); hh[1] = __float2half_rn(s1);
    hh[2] = __float2half_rn(s2); hh[3] = __float2half_rn(s3);
    ((uint2*)xh)[((size_t)b * DDIM + tid * 4) >> 2] = *(uint2*)hh;
}

// ---------------------------------------------------------------------------
extern "C" void kernel_launch(void* const* d_in, const int* in_sizes, int n_in,
                              void* d_out, int out_size)
{
    const float* X  = (const float*)d_in[0];
    const float* G  = (const float*)d_in[1];
    const float* W1 = (const float*)d_in[2];
    const float* b1 = (const float*)d_in[3];
    const float* w2 = (const float*)d_in[4];
    // d_in[5] = b2: softmax shift-invariant, unused
    const float* M1 = (const float*)d_in[6];
    const float* c1 = (const float*)d_in[7];
    const float* m2 = (const float*)d_in[8];
    const float* c2 = (const float*)d_in[9];
    float* out = (float*)d_out;

    float *E1, *E2, *ebuf;
    cudaGetSymbolAddress((void**)&E1,   E1_buf);
    cudaGetSymbolAddress((void**)&E2,   E2_buf);
    cudaGetSymbolAddress((void**)&ebuf, e_buf);

    __half *Xh, *Gh, *W1h, *M1h, *ghh, *xhh;
    cudaGetSymbolAddress((void**)&Xh,  Xh_buf);
    cudaGetSymbolAddress((void**)&Gh,  Gh_buf);
    cudaGetSymbolAddress((void**)&W1h, W1h_buf);
    cudaGetSymbolAddress((void**)&M1h, M1h_buf);
    cudaGetSymbolAddress((void**)&ghh, ghh_buf);
    cudaGetSymbolAddress((void**)&xhh, xhh_buf);

    cudaFuncSetAttribute((const void*)mma_gemm<5, true>,
                         cudaFuncAttributeMaxDynamicSharedMemorySize, SMEM_BYTES);
    cudaFuncSetAttribute((const void*)mma_gemm<4, true>,
                         cudaFuncAttributeMaxDynamicSharedMemorySize, SMEM_BYTES);
    cudaFuncSetAttribute((const void*)mma_gemm<0, false>,
                         cudaFuncAttributeMaxDynamicSharedMemorySize, SMEM_BYTES);

    // [0] convert X -> fp16
    conv_fp16_kernel<<<(BDIM * TDIM * DDIM / 4) / 256, 256>>>(X, Xh);
    // [1] convert W1 -> fp16
    conv_fp16_kernel<<<(2 * DDIM * HDIM / 4) / 256, 256>>>(W1, W1h);
    // [2] g_hat -> fp16
    gmean_kernel<<<(BDIM * DDIM) / 256, 256>>>(G, ghh);
    // [3] K2: E1 = g_hat @ W1[:512] + b1   (4096 x 1024)
    mma_gemm<0, false><<<dim3(BDIM / 128, HDIM / 128), 256, SMEM_BYTES>>>(
        ghh, W1h, b1, nullptr, nullptr, E1, HDIM);
    // [4] convert G -> fp16
    conv_fp16_kernel<<<(BDIM * KDIM * DDIM / 4) / 256, 256>>>(G, Gh);
    // [5] K3: e[b,t] = sum_h relu( X@W1[512:] + E1 ) * w2   (M = 131072)
    mma_gemm<5, true><<<(BDIM * TDIM) / 128, 256, SMEM_BYTES>>>(
        Xh, W1h + (size_t)DDIM * HDIM, E1, w2, nullptr, ebuf, HDIM);
    // [6] softmax over T + x_hat -> fp16
    softmax_xhat_kernel<<<BDIM, 128>>>(ebuf, Xh, xhh);
    // [7] convert M1 -> fp16
    conv_fp16_kernel<<<(2 * DDIM * H2DIM / 4) / 256, 256>>>(M1, M1h);
    // [8] K5: E2 = x_hat @ M1[:512] + c1   (4096 x 2048)
    mma_gemm<0, false><<<dim3(BDIM / 128, H2DIM / 128), 256, SMEM_BYTES>>>(
        xhh, M1h, c1, nullptr, nullptr, E2, H2DIM);
    // [9] K6: logits = sum_j relu( G@M1[512:] + E2 ) * m2 + c2  (M = 65536)
    mma_gemm<4, true><<<(BDIM * KDIM) / 128, 256, SMEM_BYTES>>>(
        Gh, M1h + (size_t)DDIM * H2DIM, E2, m2, c2, out, H2DIM);
}